// round 2
// baseline (speedup 1.0000x reference)
#include <cuda_runtime.h>
#include <cstdint>

#define N_NODES 16384
#define KNN 10

typedef unsigned long long u64;

// ---------------- scratch (static device allocations; no runtime alloc) ----------------
__device__ float d_E [N_NODES * 192];
__device__ float d_H [N_NODES * 128];
__device__ float d_g1[N_NODES * 64];
__device__ float d_g2[N_NODES * 64];
__device__ float d_P [N_NODES * 64];
__device__ float d_Qm[N_NODES * 64];
__device__ float d_sqn[N_NODES];
__device__ int   d_idx[N_NODES * KNN];
__device__ float d_WP[128 * 64];
__device__ float d_WQ[128 * 64];

// ---------------- packed fp32x2 helpers (Blackwell FFMA2 path) ----------------
__device__ __forceinline__ u64 pk2(float lo, float hi) {
    u64 r; asm("mov.b64 %0, {%1, %2};" : "=l"(r) : "f"(lo), "f"(hi)); return r;
}
__device__ __forceinline__ void fma2(u64& d, u64 a, u64 b) {
    asm("fma.rn.f32x2 %0, %1, %2, %0;" : "+l"(d) : "l"(a), "l"(b));
}
__device__ __forceinline__ float2 upk2(u64 v) {
    float2 f; asm("mov.b64 {%0, %1}, %2;" : "=f"(f.x), "=f"(f.y) : "l"(v)); return f;
}

// ---------------- stage 1: per-modality embeds (relu) -> E[N,192] ----------------
__global__ void embed_kernel(const float* __restrict__ nf, const float* __restrict__ rf,
                             const float* __restrict__ tf,
                             const float* __restrict__ Wb, const float* __restrict__ bb,
                             const float* __restrict__ Wr, const float* __restrict__ br,
                             const float* __restrict__ Wt, const float* __restrict__ bt)
{
    __shared__ float s[136];   // 8 node feats, 64 rf, 64 txp
    const int n = blockIdx.x;
    const int t = threadIdx.x;
    if (t < 8)                 s[t]            = nf[n * 8 + t];
    if (t >= 64 && t < 128)    s[8 + (t - 64)] = rf[n * 64 + (t - 64)];
    if (t >= 128)              s[72 + (t-128)] = tf[n * 64 + (t - 128)];
    __syncthreads();

    float acc;
    if (t < 64) {
        acc = bb[t];
        #pragma unroll
        for (int e = 0; e < 8; e++) acc = fmaf(s[e], Wb[e * 64 + t], acc);
    } else if (t < 128) {
        const int o = t - 64;
        acc = br[o];
        #pragma unroll 8
        for (int e = 0; e < 64; e++) acc = fmaf(s[8 + e], Wr[e * 64 + o], acc);
    } else {
        const int o = t - 128;
        acc = bt[o];
        #pragma unroll 8
        for (int e = 0; e < 64; e++) acc = fmaf(s[72 + e], Wt[e * 64 + o], acc);
    }
    d_E[n * 192 + t] = fmaxf(acc, 0.0f);
}

// ---------------- generic tiled fp32 GEMM: C[M,Nc] = act(A[M,Kd] @ W[Kd,Nc] + bias) ----
template <int ACT>
__global__ __launch_bounds__(256) void gemm_kernel(const float* __restrict__ A,
                                                   const float* __restrict__ W,
                                                   const float* __restrict__ bias,
                                                   float* __restrict__ C,
                                                   int Kd, int Nc)
{
    __shared__ float As[16][64];
    __shared__ float Ws[16][64];
    const int m0 = blockIdx.x * 64;
    const int n0 = blockIdx.y * 64;
    const int tid = threadIdx.x;
    const int tx = tid & 15;
    const int ty = tid >> 4;

    float acc[4][4];
    #pragma unroll
    for (int i = 0; i < 4; i++)
        #pragma unroll
        for (int j = 0; j < 4; j++) acc[i][j] = 0.0f;

    for (int k0 = 0; k0 < Kd; k0 += 16) {
        {
            const int m  = tid >> 2;
            const int kq = (tid & 3) * 4;
            float4 v = *reinterpret_cast<const float4*>(&A[(m0 + m) * Kd + k0 + kq]);
            As[kq + 0][m] = v.x; As[kq + 1][m] = v.y;
            As[kq + 2][m] = v.z; As[kq + 3][m] = v.w;
            const int kk = tid >> 4;
            const int nq = (tid & 15) * 4;
            float4 w = *reinterpret_cast<const float4*>(&W[(k0 + kk) * Nc + n0 + nq]);
            *reinterpret_cast<float4*>(&Ws[kk][nq]) = w;
        }
        __syncthreads();
        #pragma unroll
        for (int k = 0; k < 16; k++) {
            float4 a = *reinterpret_cast<const float4*>(&As[k][ty * 4]);
            float4 b = *reinterpret_cast<const float4*>(&Ws[k][tx * 4]);
            float av[4] = {a.x, a.y, a.z, a.w};
            float bv[4] = {b.x, b.y, b.z, b.w};
            #pragma unroll
            for (int i = 0; i < 4; i++)
                #pragma unroll
                for (int j = 0; j < 4; j++)
                    acc[i][j] = fmaf(av[i], bv[j], acc[i][j]);
        }
        __syncthreads();
    }

    #pragma unroll
    for (int i = 0; i < 4; i++) {
        const int m = m0 + ty * 4 + i;
        #pragma unroll
        for (int j = 0; j < 4; j++) {
            const int n = n0 + tx * 4 + j;
            float v = acc[i][j] + (bias ? bias[n] : 0.0f);
            if (ACT == 2) v = (v > 0.0f) ? v : 0.01f * v;
            C[m * Nc + n] = v;
        }
    }
}

// ---------------- squared norms ----------------
__global__ void sqnorm_kernel(const float* __restrict__ X, float* __restrict__ out, int D)
{
    const int n    = blockIdx.x * 8 + (threadIdx.x >> 5);
    const int lane = threadIdx.x & 31;
    float s = 0.0f;
    for (int d = lane; d < D; d += 32) { float v = X[n * D + d]; s = fmaf(v, v, s); }
    #pragma unroll
    for (int o = 16; o > 0; o >>= 1) s += __shfl_xor_sync(0xFFFFFFFFu, s, o);
    if (lane == 0) out[n] = s;
}

// ---------------- top-k insert helper ----------------
__device__ __forceinline__ void topk_insert(float (&topd)[KNN], int (&topi)[KNN],
                                            float dd, int ci)
{
    topd[KNN - 1] = dd; topi[KNN - 1] = ci;
    #pragma unroll
    for (int z = KNN - 2; z >= 0; z--) {
        if (topd[z] > topd[z + 1]) {
            float td = topd[z]; topd[z] = topd[z + 1]; topd[z + 1] = td;
            int   ti = topi[z]; topi[z] = topi[z + 1]; topi[z + 1] = ti;
        }
    }
}

// ---------------- fused KNN: packed-FFMA2 Gram tiles + running top-10 ----------------
// 128 queries per block, 128-candidate tiles, 256 threads, 8x8 microtiles via f32x2.
// NOTE: scanned "distance" is sqc[c] - 2*gram (per-query constant sqq dropped —
// does not change per-query top-k ordering; self excluded explicitly).
template <int D>
__global__ __launch_bounds__(256, 1) void knn_kernel(const float* __restrict__ X,
                                                     const float* __restrict__ sqn,
                                                     int* __restrict__ outIdx)
{
    extern __shared__ float sm[];
    float* qt  = sm;             // D*128 floats (transposed queries)
    float* scr = sm + D * 128;   // 16896 floats: union{ ct[D][128], dist[128][132], merge }
    __shared__ float sqc[128];

    const int tid = threadIdx.x;
    const int q0  = blockIdx.x * 128;
    const int tx  = tid & 15;
    const int ty  = tid >> 4;

    // load query tile transposed: qt[d][q]
    for (int i = tid; i < 128 * (D / 4); i += 256) {
        const int q  = i / (D / 4);
        const int dq = (i % (D / 4)) * 4;
        float4 v = *reinterpret_cast<const float4*>(&X[(q0 + q) * D + dq]);
        qt[(dq + 0) * 128 + q] = v.x; qt[(dq + 1) * 128 + q] = v.y;
        qt[(dq + 2) * 128 + q] = v.z; qt[(dq + 3) * 128 + q] = v.w;
    }

    float topd[KNN]; int topi[KNN];
    #pragma unroll
    for (int i = 0; i < KNN; i++) { topd[i] = 1e30f; topi[i] = 0; }

    const int qmine = tid & 127;        // query owned for scanning
    const int cbase = (tid >> 7) * 64;  // half of the candidate tile

    for (int c0 = 0; c0 < N_NODES; c0 += 128) {
        __syncthreads();   // previous scan done before scr is overwritten
        // load candidate tile transposed into scr: ct[d][c]
        for (int i = tid; i < 128 * (D / 4); i += 256) {
            const int c  = i / (D / 4);
            const int dq = (i % (D / 4)) * 4;
            float4 v = *reinterpret_cast<const float4*>(&X[(c0 + c) * D + dq]);
            scr[(dq + 0) * 128 + c] = v.x; scr[(dq + 1) * 128 + c] = v.y;
            scr[(dq + 2) * 128 + c] = v.z; scr[(dq + 3) * 128 + c] = v.w;
        }
        if (tid < 128) sqc[tid] = sqn[c0 + tid];
        __syncthreads();

        // -------- packed Gram accumulation: acc2[i][j] holds candidates (2j, 2j+1) ----
        u64 acc2[8][4];
        #pragma unroll
        for (int i = 0; i < 8; i++)
            #pragma unroll
            for (int j = 0; j < 4; j++) acc2[i][j] = 0ull;

        #pragma unroll 4
        for (int k = 0; k < D; k++) {
            float4 a0 = *reinterpret_cast<const float4*>(&qt[k * 128 + ty * 8]);
            float4 a1 = *reinterpret_cast<const float4*>(&qt[k * 128 + ty * 8 + 4]);
            float4 b0 = *reinterpret_cast<const float4*>(&scr[k * 128 + tx * 8]);
            float4 b1 = *reinterpret_cast<const float4*>(&scr[k * 128 + tx * 8 + 4]);
            u64 bp[4] = { pk2(b0.x, b0.y), pk2(b0.z, b0.w),
                          pk2(b1.x, b1.y), pk2(b1.z, b1.w) };
            float av[8] = {a0.x, a0.y, a0.z, a0.w, a1.x, a1.y, a1.z, a1.w};
            #pragma unroll
            for (int i = 0; i < 8; i++) {
                const u64 ap = pk2(av[i], av[i]);
                #pragma unroll
                for (int j = 0; j < 4; j++) fma2(acc2[i][j], ap, bp[j]);
            }
        }
        __syncthreads();   // done reading scr as ct

        // distances into scr as dist[q][132], float4 stores
        #pragma unroll
        for (int i = 0; i < 8; i++) {
            const int q = ty * 8 + i;
            #pragma unroll
            for (int jj = 0; jj < 2; jj++) {
                float2 g0 = upk2(acc2[i][jj * 2 + 0]);
                float2 g1 = upk2(acc2[i][jj * 2 + 1]);
                const int c = tx * 8 + jj * 4;
                float4 dv;
                dv.x = fmaf(-2.0f, g0.x, sqc[c + 0]);
                dv.y = fmaf(-2.0f, g0.y, sqc[c + 1]);
                dv.z = fmaf(-2.0f, g1.x, sqc[c + 2]);
                dv.w = fmaf(-2.0f, g1.y, sqc[c + 3]);
                if (q0 + q - c0 - c == 0) dv.x = 1e30f;
                if (q0 + q - c0 - c == 1) dv.y = 1e30f;
                if (q0 + q - c0 - c == 2) dv.z = 1e30f;
                if (q0 + q - c0 - c == 3) dv.w = 1e30f;
                *reinterpret_cast<float4*>(&scr[q * 132 + c]) = dv;
            }
        }
        __syncthreads();

        // scan: 2 threads per query, 64 candidates each, float4 reads
        const float* row = &scr[qmine * 132 + cbase];
        #pragma unroll
        for (int cc = 0; cc < 16; cc++) {
            float4 v = *reinterpret_cast<const float4*>(&row[cc * 4]);
            const int ci = c0 + cbase + cc * 4;
            if (v.x < topd[KNN - 1]) topk_insert(topd, topi, v.x, ci + 0);
            if (v.y < topd[KNN - 1]) topk_insert(topd, topi, v.y, ci + 1);
            if (v.z < topd[KNN - 1]) topk_insert(topd, topi, v.z, ci + 2);
            if (v.w < topd[KNN - 1]) topk_insert(topd, topi, v.w, ci + 3);
        }
    }

    // merge the two per-query halves
    __syncthreads();
    if (tid >= 128) {
        const int q = tid - 128;
        #pragma unroll
        for (int i = 0; i < KNN; i++) {
            scr[q * 2 * KNN + i] = topd[i];
            reinterpret_cast<int*>(scr)[q * 2 * KNN + KNN + i] = topi[i];
        }
    }
    __syncthreads();
    if (tid < 128) {
        #pragma unroll
        for (int i = 0; i < KNN; i++) {
            const float dd = scr[tid * 2 * KNN + i];
            const int   ci = reinterpret_cast<int*>(scr)[tid * 2 * KNN + KNN + i];
            if (dd < topd[KNN - 1]) topk_insert(topd, topi, dd, ci);
        }
        #pragma unroll
        for (int i = 0; i < KNN; i++) outIdx[(q0 + tid) * KNN + i] = topi[i];
    }
}

// ---------------- EdgeConv weight split: WP = Wa - Wb, WQ = Wb ----------------
__global__ void prepw_kernel(const float* __restrict__ We, int D)
{
    const int i = blockIdx.x * 256 + threadIdx.x;
    if (i < D * 64) {
        const float b = We[D * 64 + i];
        d_WQ[i] = b;
        d_WP[i] = We[i] - b;
    }
}

// ---------------- EdgeConv aggregation: g[n,o] = max_k leaky(P[n,o] + Q[idx[n,k],o]) ----
__global__ void maxagg_kernel(const float* __restrict__ P, const float* __restrict__ Q,
                              const int* __restrict__ idx, float* __restrict__ g)
{
    const int tid = threadIdx.x;
    const int n = blockIdx.x * 4 + (tid >> 6);
    const int o = tid & 63;
    const float p = P[n * 64 + o];
    float m = -1e30f;
    #pragma unroll
    for (int kk = 0; kk < KNN; kk++) {
        const int j = idx[n * KNN + kk];
        float v = p + Q[j * 64 + o];
        v = (v > 0.0f) ? v : 0.01f * v;
        m = fmaxf(m, v);
    }
    g[n * 64 + o] = m;
}

// ---------------- classifier: logits = [g1,g2] @ Wc + bc ----------------
__global__ void classifier_kernel(const float* __restrict__ Wc, const float* __restrict__ bc,
                                  float* __restrict__ out)
{
    const int tid = threadIdx.x;
    const int n = blockIdx.x * 16 + (tid >> 4);
    const int c = tid & 15;
    float acc = bc[c];
    const float* g1r = d_g1 + n * 64;
    const float* g2r = d_g2 + n * 64;
    #pragma unroll 8
    for (int o = 0; o < 64; o++) {
        acc = fmaf(g1r[o], Wc[o * 16 + c], acc);
        acc = fmaf(g2r[o], Wc[(64 + o) * 16 + c], acc);
    }
    out[n * 16 + c] = acc;
}

// ---------------- launch ----------------
extern "C" void kernel_launch(void* const* d_in, const int* in_sizes, int n_in,
                              void* d_out, int out_size)
{
    const float* node_feat = (const float*)d_in[0];
    const float* rf_feat   = (const float*)d_in[1];
    const float* txp_feat  = (const float*)d_in[2];
    const float* Wb  = (const float*)d_in[3];
    const float* bb  = (const float*)d_in[4];
    const float* Wr  = (const float*)d_in[5];
    const float* br  = (const float*)d_in[6];
    const float* Wt  = (const float*)d_in[7];
    const float* bt  = (const float*)d_in[8];
    const float* Wf  = (const float*)d_in[9];
    const float* bf  = (const float*)d_in[10];
    const float* We1 = (const float*)d_in[11];
    const float* be1 = (const float*)d_in[12];
    const float* We2 = (const float*)d_in[13];
    const float* be2 = (const float*)d_in[14];
    const float* Wc  = (const float*)d_in[15];
    const float* bc  = (const float*)d_in[16];
    float* out = (float*)d_out;

    void *pE, *pH, *pg1, *pg2, *pP, *pQ, *psqn, *pidx, *pWP, *pWQ;
    cudaGetSymbolAddress(&pE,   d_E);
    cudaGetSymbolAddress(&pH,   d_H);
    cudaGetSymbolAddress(&pg1,  d_g1);
    cudaGetSymbolAddress(&pg2,  d_g2);
    cudaGetSymbolAddress(&pP,   d_P);
    cudaGetSymbolAddress(&pQ,   d_Qm);
    cudaGetSymbolAddress(&psqn, d_sqn);
    cudaGetSymbolAddress(&pidx, d_idx);
    cudaGetSymbolAddress(&pWP,  d_WP);
    cudaGetSymbolAddress(&pWQ,  d_WQ);

    const int SCR = 16896;
    const int smem1 = (128 * 128 + SCR) * 4;
    const int smem2 = (64  * 128 + SCR) * 4;
    cudaFuncSetAttribute(knn_kernel<128>, cudaFuncAttributeMaxDynamicSharedMemorySize, smem1);
    cudaFuncSetAttribute(knn_kernel<64>,  cudaFuncAttributeMaxDynamicSharedMemorySize, smem2);

    // stage 1: embeds + fusion
    embed_kernel<<<N_NODES, 192>>>(node_feat, rf_feat, txp_feat, Wb, bb, Wr, br, Wt, bt);
    gemm_kernel<2><<<dim3(N_NODES / 64, 2), 256>>>((const float*)pE, Wf, bf, (float*)pH, 192, 128);

    // EdgeConv 1
    sqnorm_kernel<<<N_NODES / 8, 256>>>((const float*)pH, (float*)psqn, 128);
    knn_kernel<128><<<128, 256, smem1>>>((const float*)pH, (const float*)psqn, (int*)pidx);
    prepw_kernel<<<(128 * 64 + 255) / 256, 256>>>(We1, 128);
    gemm_kernel<0><<<dim3(N_NODES / 64, 1), 256>>>((const float*)pH, (const float*)pWP, be1,
                                                   (float*)pP, 128, 64);
    gemm_kernel<0><<<dim3(N_NODES / 64, 1), 256>>>((const float*)pH, (const float*)pWQ, nullptr,
                                                   (float*)pQ, 128, 64);
    maxagg_kernel<<<N_NODES / 4, 256>>>((const float*)pP, (const float*)pQ,
                                        (const int*)pidx, (float*)pg1);

    // EdgeConv 2
    sqnorm_kernel<<<N_NODES / 8, 256>>>((const float*)pg1, (float*)psqn, 64);
    knn_kernel<64><<<128, 256, smem2>>>((const float*)pg1, (const float*)psqn, (int*)pidx);
    prepw_kernel<<<(64 * 64 + 255) / 256, 256>>>(We2, 64);
    gemm_kernel<0><<<dim3(N_NODES / 64, 1), 256>>>((const float*)pg1, (const float*)pWP, be2,
                                                   (float*)pP, 64, 64);
    gemm_kernel<0><<<dim3(N_NODES / 64, 1), 256>>>((const float*)pg1, (const float*)pWQ, nullptr,
                                                   (float*)pQ, 64, 64);
    maxagg_kernel<<<N_NODES / 4, 256>>>((const float*)pP, (const float*)pQ,
                                        (const int*)pidx, (float*)pg2);

    // classifier
    classifier_kernel<<<N_NODES / 16, 256>>>(Wc, bc, out);
}

// round 5
// speedup vs baseline: 1.0229x; 1.0229x over previous
#include <cuda_runtime.h>
#include <cuda_bf16.h>
#include <cstdint>

#define N_NODES 16384
#define KNN 10
#define CAND 16   // approx candidates kept per query for exact rescoring

// ---------------- scratch (static device allocations; no runtime alloc) ----------------
__device__ float d_E [N_NODES * 192];
__device__ float d_H [N_NODES * 128];
__device__ float d_g1[N_NODES * 64];
__device__ float d_g2[N_NODES * 64];
__device__ float d_P [N_NODES * 64];
__device__ float d_Qm[N_NODES * 64];
__device__ float d_sqn[N_NODES];
__device__ int   d_idx[N_NODES * KNN];
__device__ int   d_cand[N_NODES * CAND];
__device__ float d_WP[128 * 64];
__device__ float d_WQ[128 * 64];
__device__ __nv_bfloat16 d_X2[N_NODES * 256];   // [hi | lo] split, up to 2*128 cols

// ---------------- PTX helpers (generic sm_80+ features only) ----------------
__device__ __forceinline__ uint32_t smem_u32(const void* p) {
    uint32_t a;
    asm("{ .reg .u64 t; cvta.to.shared.u64 t, %1; cvt.u32.u64 %0, t; }" : "=r"(a) : "l"(p));
    return a;
}
#define CP_ASYNC16(dst, src) \
    asm volatile("cp.async.cg.shared.global [%0], [%1], 16;" :: "r"(dst), "l"(src))
#define CP_COMMIT() asm volatile("cp.async.commit_group;" ::: "memory")
#define CP_WAIT0()  asm volatile("cp.async.wait_group 0;" ::: "memory")

#define LDSM4(r0, r1, r2, r3, addr) \
    asm volatile("ldmatrix.sync.aligned.m8n8.x4.shared.b16 {%0,%1,%2,%3}, [%4];" \
                 : "=r"(r0), "=r"(r1), "=r"(r2), "=r"(r3) : "r"(addr))

#define MMA16816(d, a, b) \
    asm volatile("mma.sync.aligned.m16n8k16.row.col.f32.bf16.bf16.f32 " \
                 "{%0,%1,%2,%3}, {%4,%5,%6,%7}, {%8,%9}, {%0,%1,%2,%3};" \
                 : "+f"((d)[0]), "+f"((d)[1]), "+f"((d)[2]), "+f"((d)[3]) \
                 : "r"((a)[0]), "r"((a)[1]), "r"((a)[2]), "r"((a)[3]), \
                   "r"((b)[0]), "r"((b)[1]))

// ---------------- stage 1: per-modality embeds (relu) -> E[N,192] ----------------
__global__ void embed_kernel(const float* __restrict__ nf, const float* __restrict__ rf,
                             const float* __restrict__ tf,
                             const float* __restrict__ Wb, const float* __restrict__ bb,
                             const float* __restrict__ Wr, const float* __restrict__ br,
                             const float* __restrict__ Wt, const float* __restrict__ bt)
{
    __shared__ float s[136];
    const int n = blockIdx.x;
    const int t = threadIdx.x;
    if (t < 8)                 s[t]            = nf[n * 8 + t];
    if (t >= 64 && t < 128)    s[8 + (t - 64)] = rf[n * 64 + (t - 64)];
    if (t >= 128)              s[72 + (t-128)] = tf[n * 64 + (t - 128)];
    __syncthreads();

    float acc;
    if (t < 64) {
        acc = bb[t];
        #pragma unroll
        for (int e = 0; e < 8; e++) acc = fmaf(s[e], Wb[e * 64 + t], acc);
    } else if (t < 128) {
        const int o = t - 64;
        acc = br[o];
        #pragma unroll 8
        for (int e = 0; e < 64; e++) acc = fmaf(s[8 + e], Wr[e * 64 + o], acc);
    } else {
        const int o = t - 128;
        acc = bt[o];
        #pragma unroll 8
        for (int e = 0; e < 64; e++) acc = fmaf(s[72 + e], Wt[e * 64 + o], acc);
    }
    d_E[n * 192 + t] = fmaxf(acc, 0.0f);
}

// ---------------- generic tiled fp32 GEMM ----------------
template <int ACT>
__global__ __launch_bounds__(256) void gemm_kernel(const float* __restrict__ A,
                                                   const float* __restrict__ W,
                                                   const float* __restrict__ bias,
                                                   float* __restrict__ C,
                                                   int Kd, int Nc)
{
    __shared__ float As[16][64];
    __shared__ float Ws[16][64];
    const int m0 = blockIdx.x * 64;
    const int n0 = blockIdx.y * 64;
    const int tid = threadIdx.x;
    const int tx = tid & 15;
    const int ty = tid >> 4;

    float acc[4][4];
    #pragma unroll
    for (int i = 0; i < 4; i++)
        #pragma unroll
        for (int j = 0; j < 4; j++) acc[i][j] = 0.0f;

    for (int k0 = 0; k0 < Kd; k0 += 16) {
        {
            const int m  = tid >> 2;
            const int kq = (tid & 3) * 4;
            float4 v = *reinterpret_cast<const float4*>(&A[(m0 + m) * Kd + k0 + kq]);
            As[kq + 0][m] = v.x; As[kq + 1][m] = v.y;
            As[kq + 2][m] = v.z; As[kq + 3][m] = v.w;
            const int kk = tid >> 4;
            const int nq = (tid & 15) * 4;
            float4 w = *reinterpret_cast<const float4*>(&W[(k0 + kk) * Nc + n0 + nq]);
            *reinterpret_cast<float4*>(&Ws[kk][nq]) = w;
        }
        __syncthreads();
        #pragma unroll
        for (int k = 0; k < 16; k++) {
            float4 a = *reinterpret_cast<const float4*>(&As[k][ty * 4]);
            float4 b = *reinterpret_cast<const float4*>(&Ws[k][tx * 4]);
            float av[4] = {a.x, a.y, a.z, a.w};
            float bv[4] = {b.x, b.y, b.z, b.w};
            #pragma unroll
            for (int i = 0; i < 4; i++)
                #pragma unroll
                for (int j = 0; j < 4; j++)
                    acc[i][j] = fmaf(av[i], bv[j], acc[i][j]);
        }
        __syncthreads();
    }

    #pragma unroll
    for (int i = 0; i < 4; i++) {
        const int m = m0 + ty * 4 + i;
        #pragma unroll
        for (int j = 0; j < 4; j++) {
            const int n = n0 + tx * 4 + j;
            float v = acc[i][j] + (bias ? bias[n] : 0.0f);
            if (ACT == 2) v = (v > 0.0f) ? v : 0.01f * v;
            C[m * Nc + n] = v;
        }
    }
}

// ---------------- squared norms (exact fp32) ----------------
__global__ void sqnorm_kernel(const float* __restrict__ X, float* __restrict__ out, int D)
{
    const int n    = blockIdx.x * 8 + (threadIdx.x >> 5);
    const int lane = threadIdx.x & 31;
    float s = 0.0f;
    for (int d = lane; d < D; d += 32) { float v = X[n * D + d]; s = fmaf(v, v, s); }
    #pragma unroll
    for (int o = 16; o > 0; o >>= 1) s += __shfl_xor_sync(0xFFFFFFFFu, s, o);
    if (lane == 0) out[n] = s;
}

// ---------------- hi/lo bf16 split: X[N,D] fp32 -> X2[N, 2D] bf16 ----------------
__global__ void split_kernel(const float* __restrict__ X, int D)
{
    const int i = blockIdx.x * 256 + threadIdx.x;
    const int n = i / D;
    const int d = i - n * D;
    const float x = X[i];
    const __nv_bfloat16 hi = __float2bfloat16(x);
    const float r = x - __bfloat162float(hi);
    const __nv_bfloat16 lo = __float2bfloat16(r);
    d_X2[n * 2 * D + d]     = hi;
    d_X2[n * 2 * D + D + d] = lo;
}

// ---------------- top-k insert (generic length) ----------------
template <int M>
__device__ __forceinline__ void topk_insert(float (&topd)[M], int (&topi)[M],
                                            float dd, int ci)
{
    topd[M - 1] = dd; topi[M - 1] = ci;
    #pragma unroll
    for (int z = M - 2; z >= 0; z--) {
        if (topd[z] > topd[z + 1]) {
            float td = topd[z]; topd[z] = topd[z + 1]; topd[z + 1] = td;
            int   ti = topi[z]; topi[z] = topi[z + 1]; topi[z + 1] = ti;
        }
    }
}

// ---------------- approx KNN via mma.sync (HMMA bf16, 3-term hi/lo split) --------
// Emits top-CAND candidate indices per query; exact rescoring picks final top-10.
template <int D>
__global__ __launch_bounds__(256, 1) void knn_mma_kernel(const float* __restrict__ sqn,
                                                         int* __restrict__ outCand)
{
    constexpr int PAD   = 8;
    constexpr int PB    = (2 * D + PAD) * 2;    // smem row pitch in bytes
    constexpr int TILEB = 128 * PB;
    constexpr int CH    = D / 4;                // 16B chunks per row
    constexpr bool ALIAS = (D == 128);

    extern __shared__ char smch[];
    char* qt  = smch;
    char* ct0 = smch + TILEB;
    char* ct1 = smch + 2 * TILEB;

    __shared__ float s_sqc[2][128];
    __shared__ float s_mg [128 * CAND];
    __shared__ int   s_mgi[128 * CAND];

    const int tid  = threadIdx.x;
    const int wid  = tid >> 5;
    const int lane = tid & 31;
    const int q0   = blockIdx.x * 128;

    const int mrow = (wid & 1) * 64;
    const int ncol = (wid >> 1) * 32;
    const int lrow = lane & 15;
    const int lkof = (lane >> 4) * 16;

    const uint32_t qtu  = smem_u32(qt);
    const uint32_t ctu0 = smem_u32(ct0);
    const uint32_t ctu1 = smem_u32(ct1);
    const uint32_t aBase = qtu + (mrow + lrow) * PB + lkof;
    const uint32_t bOff  = (ncol + lrow) * PB + lkof;

    {
        #pragma unroll 4
        for (int i = tid; i < 128 * CH; i += 256) {
            const int r  = i / CH;
            const int ch = i - r * CH;
            CP_ASYNC16(qtu + r * PB + ch * 16,
                       d_X2 + (size_t)(q0 + r) * (2 * D) + ch * 8);
        }
        #pragma unroll 4
        for (int i = tid; i < 128 * CH; i += 256) {
            const int r  = i / CH;
            const int ch = i - r * CH;
            CP_ASYNC16(ctu0 + r * PB + ch * 16,
                       d_X2 + (size_t)r * (2 * D) + ch * 8);
        }
        CP_COMMIT();
        if (tid < 128) s_sqc[0][tid] = sqn[tid];
    }

    float topd[CAND]; int topi[CAND];
    #pragma unroll
    for (int i = 0; i < CAND; i++) { topd[i] = 1e30f; topi[i] = 0; }

    const int qmine = tid & 127;
    const int cbase = (tid >> 7) * 64;

    const int T = N_NODES / 128;
    for (int t = 0; t < T; t++) {
        CP_WAIT0();
        __syncthreads();

        const uint32_t ctu = (t & 1) ? ctu1 : ctu0;
        if (t + 1 < T) {
            const uint32_t ctn = ((t + 1) & 1) ? ctu1 : ctu0;
            const int r0n = (t + 1) * 128;
            #pragma unroll 4
            for (int i = tid; i < 128 * CH; i += 256) {
                const int r  = i / CH;
                const int ch = i - r * CH;
                CP_ASYNC16(ctn + r * PB + ch * 16,
                           d_X2 + (size_t)(r0n + r) * (2 * D) + ch * 8);
            }
            CP_COMMIT();
            if (tid < 128) s_sqc[(t + 1) & 1][tid] = sqn[r0n + tid];
        }

        float acc[4][4][4];
        #pragma unroll
        for (int mt = 0; mt < 4; mt++)
            #pragma unroll
            for (int nt = 0; nt < 4; nt++)
                #pragma unroll
                for (int r = 0; r < 4; r++) acc[mt][nt][r] = 0.0f;

        const uint32_t bBase = ctu + bOff;
        #pragma unroll
        for (int term = 0; term < 3; term++) {
            const int ka = (term == 1) ? D : 0;
            const int kb = (term == 2) ? D : 0;
            #pragma unroll
            for (int kc = 0; kc < D; kc += 16) {
                uint32_t a[4][4];
                #pragma unroll
                for (int mt = 0; mt < 4; mt++)
                    LDSM4(a[mt][0], a[mt][1], a[mt][2], a[mt][3],
                          aBase + mt * 16 * PB + (ka + kc) * 2);
                uint32_t b[4][2];
                #pragma unroll
                for (int nb = 0; nb < 2; nb++) {
                    uint32_t r0, r1, r2, r3;
                    LDSM4(r0, r1, r2, r3, bBase + nb * 16 * PB + (kb + kc) * 2);
                    b[nb * 2][0] = r0; b[nb * 2][1] = r2;
                    b[nb * 2 + 1][0] = r1; b[nb * 2 + 1][1] = r3;
                }
                #pragma unroll
                for (int mt = 0; mt < 4; mt++)
                    #pragma unroll
                    for (int nt = 0; nt < 4; nt++)
                        MMA16816(acc[mt][nt], a[mt], b[nt]);
            }
        }
        __syncthreads();

        float* dist = ALIAS ? reinterpret_cast<float*>((t & 1) ? ct1 : ct0)
                            : reinterpret_cast<float*>(smch + 3 * TILEB);
        const float* sq = s_sqc[t & 1];
        const int c0 = t * 128;

        #pragma unroll
        for (int mt = 0; mt < 4; mt++) {
            const int qA = mrow + mt * 16 + (lane >> 2);
            #pragma unroll
            for (int nt = 0; nt < 4; nt++) {
                const int c = ncol + nt * 8 + (lane & 3) * 2;
                const float s0 = sq[c], s1 = sq[c + 1];
                float2 v0, v1;
                v0.x = fmaf(-2.0f, acc[mt][nt][0], s0);
                v0.y = fmaf(-2.0f, acc[mt][nt][1], s1);
                v1.x = fmaf(-2.0f, acc[mt][nt][2], s0);
                v1.y = fmaf(-2.0f, acc[mt][nt][3], s1);
                const int dq = (q0 + qA) - (c0 + c);
                if (dq ==  0) v0.x = 1e30f;
                if (dq ==  1) v0.y = 1e30f;
                if (dq == -8) v1.x = 1e30f;
                if (dq == -7) v1.y = 1e30f;
                *reinterpret_cast<float2*>(&dist[qA * 132 + c])       = v0;
                *reinterpret_cast<float2*>(&dist[(qA + 8) * 132 + c]) = v1;
            }
        }
        __syncthreads();

        const float* row = &dist[qmine * 132 + cbase];
        #pragma unroll
        for (int cc = 0; cc < 16; cc++) {
            float4 v = *reinterpret_cast<const float4*>(&row[cc * 4]);
            const int ci = c0 + cbase + cc * 4;
            if (v.x < topd[CAND - 1]) topk_insert(topd, topi, v.x, ci + 0);
            if (v.y < topd[CAND - 1]) topk_insert(topd, topi, v.y, ci + 1);
            if (v.z < topd[CAND - 1]) topk_insert(topd, topi, v.z, ci + 2);
            if (v.w < topd[CAND - 1]) topk_insert(topd, topi, v.w, ci + 3);
        }
    }

    // merge the two per-query halves -> exact approx-top-CAND
    __syncthreads();
    if (tid >= 128) {
        const int qq = tid - 128;
        #pragma unroll
        for (int i = 0; i < CAND; i++) {
            s_mg [qq * CAND + i] = topd[i];
            s_mgi[qq * CAND + i] = topi[i];
        }
    }
    __syncthreads();
    if (tid < 128) {
        #pragma unroll
        for (int i = 0; i < CAND; i++) {
            const float dd = s_mg[tid * CAND + i];
            if (dd < topd[CAND - 1]) topk_insert(topd, topi, dd, s_mgi[tid * CAND + i]);
        }
        #pragma unroll
        for (int i = 0; i < CAND; i++) outCand[(q0 + tid) * CAND + i] = topi[i];
    }
}

// ---------------- exact fp32 rescore: top-KNN of CAND candidates per query -------
template <int D>
__global__ void rescore_kernel(const float* __restrict__ X, const float* __restrict__ sqn,
                               const int* __restrict__ cand, int* __restrict__ outIdx)
{
    constexpr int PL = D / 32;     // floats per lane
    const int wid  = threadIdx.x >> 5;
    const int lane = threadIdx.x & 31;
    const int q    = blockIdx.x * 8 + wid;

    float xq[PL];
    #pragma unroll
    for (int i = 0; i < PL; i++) xq[i] = X[q * D + i * 32 + lane];

    float topd[KNN]; int topi[KNN];
    #pragma unroll
    for (int i = 0; i < KNN; i++) { topd[i] = 1e30f; topi[i] = 0; }

    #pragma unroll
    for (int j = 0; j < CAND; j++) {
        const int c = cand[q * CAND + j];
        float dot = 0.0f;
        #pragma unroll
        for (int i = 0; i < PL; i++) dot = fmaf(xq[i], X[c * D + i * 32 + lane], dot);
        #pragma unroll
        for (int o = 16; o > 0; o >>= 1) dot += __shfl_xor_sync(0xFFFFFFFFu, dot, o);
        const float dd = fmaf(-2.0f, dot, sqn[c]);
        if (dd < topd[KNN - 1]) topk_insert(topd, topi, dd, c);
    }
    if (lane == 0) {
        #pragma unroll
        for (int i = 0; i < KNN; i++) outIdx[q * KNN + i] = topi[i];
    }
}

// ---------------- EdgeConv weight split: WP = Wa - Wb, WQ = Wb ----------------
__global__ void prepw_kernel(const float* __restrict__ We, int D)
{
    const int i = blockIdx.x * 256 + threadIdx.x;
    if (i < D * 64) {
        const float b = We[D * 64 + i];
        d_WQ[i] = b;
        d_WP[i] = We[i] - b;
    }
}

// ---------------- EdgeConv aggregation ----------------
__global__ void maxagg_kernel(const float* __restrict__ P, const float* __restrict__ Q,
                              const int* __restrict__ idx, float* __restrict__ g)
{
    const int tid = threadIdx.x;
    const int n = blockIdx.x * 4 + (tid >> 6);
    const int o = tid & 63;
    const float p = P[n * 64 + o];
    float m = -1e30f;
    #pragma unroll
    for (int kk = 0; kk < KNN; kk++) {
        const int j = idx[n * KNN + kk];
        float v = p + Q[j * 64 + o];
        v = (v > 0.0f) ? v : 0.01f * v;
        m = fmaxf(m, v);
    }
    g[n * 64 + o] = m;
}

// ---------------- classifier ----------------
__global__ void classifier_kernel(const float* __restrict__ Wc, const float* __restrict__ bc,
                                  float* __restrict__ out)
{
    const int tid = threadIdx.x;
    const int n = blockIdx.x * 16 + (tid >> 4);
    const int c = tid & 15;
    float acc = bc[c];
    const float* g1r = d_g1 + n * 64;
    const float* g2r = d_g2 + n * 64;
    #pragma unroll 8
    for (int o = 0; o < 64; o++) {
        acc = fmaf(g1r[o], Wc[o * 16 + c], acc);
        acc = fmaf(g2r[o], Wc[(64 + o) * 16 + c], acc);
    }
    out[n * 16 + c] = acc;
}

// ---------------- launch ----------------
extern "C" void kernel_launch(void* const* d_in, const int* in_sizes, int n_in,
                              void* d_out, int out_size)
{
    const float* node_feat = (const float*)d_in[0];
    const float* rf_feat   = (const float*)d_in[1];
    const float* txp_feat  = (const float*)d_in[2];
    const float* Wb  = (const float*)d_in[3];
    const float* bb  = (const float*)d_in[4];
    const float* Wr  = (const float*)d_in[5];
    const float* br  = (const float*)d_in[6];
    const float* Wt  = (const float*)d_in[7];
    const float* bt  = (const float*)d_in[8];
    const float* Wf  = (const float*)d_in[9];
    const float* bf  = (const float*)d_in[10];
    const float* We1 = (const float*)d_in[11];
    const float* be1 = (const float*)d_in[12];
    const float* We2 = (const float*)d_in[13];
    const float* be2 = (const float*)d_in[14];
    const float* Wc  = (const float*)d_in[15];
    const float* bc  = (const float*)d_in[16];
    float* out = (float*)d_out;

    void *pE, *pH, *pg1, *pg2, *pP, *pQ, *psqn, *pidx, *pcand, *pWP, *pWQ;
    cudaGetSymbolAddress(&pE,    d_E);
    cudaGetSymbolAddress(&pH,    d_H);
    cudaGetSymbolAddress(&pg1,   d_g1);
    cudaGetSymbolAddress(&pg2,   d_g2);
    cudaGetSymbolAddress(&pP,    d_P);
    cudaGetSymbolAddress(&pQ,    d_Qm);
    cudaGetSymbolAddress(&psqn,  d_sqn);
    cudaGetSymbolAddress(&pidx,  d_idx);
    cudaGetSymbolAddress(&pcand, d_cand);
    cudaGetSymbolAddress(&pWP,   d_WP);
    cudaGetSymbolAddress(&pWQ,   d_WQ);

    const int smem1 = 3 * 128 * 528;
    const int smem2 = 3 * 128 * 272 + 128 * 132 * 4;
    cudaFuncSetAttribute(knn_mma_kernel<128>, cudaFuncAttributeMaxDynamicSharedMemorySize, smem1);
    cudaFuncSetAttribute(knn_mma_kernel<64>,  cudaFuncAttributeMaxDynamicSharedMemorySize, smem2);

    // stage 1: embeds + fusion
    embed_kernel<<<N_NODES, 192>>>(node_feat, rf_feat, txp_feat, Wb, bb, Wr, br, Wt, bt);
    gemm_kernel<2><<<dim3(N_NODES / 64, 2), 256>>>((const float*)pE, Wf, bf, (float*)pH, 192, 128);

    // EdgeConv 1
    sqnorm_kernel<<<N_NODES / 8, 256>>>((const float*)pH, (float*)psqn, 128);
    split_kernel<<<N_NODES * 128 / 256, 256>>>((const float*)pH, 128);
    knn_mma_kernel<128><<<128, 256, smem1>>>((const float*)psqn, (int*)pcand);
    rescore_kernel<128><<<N_NODES / 8, 256>>>((const float*)pH, (const float*)psqn,
                                              (const int*)pcand, (int*)pidx);
    prepw_kernel<<<(128 * 64 + 255) / 256, 256>>>(We1, 128);
    gemm_kernel<0><<<dim3(N_NODES / 64, 1), 256>>>((const float*)pH, (const float*)pWP, be1,
                                                   (float*)pP, 128, 64);
    gemm_kernel<0><<<dim3(N_NODES / 64, 1), 256>>>((const float*)pH, (const float*)pWQ, nullptr,
                                                   (float*)pQ, 128, 64);
    maxagg_kernel<<<N_NODES / 4, 256>>>((const float*)pP, (const float*)pQ,
                                        (const int*)pidx, (float*)pg1);

    // EdgeConv 2
    sqnorm_kernel<<<N_NODES / 8, 256>>>((const float*)pg1, (float*)psqn, 64);
    split_kernel<<<N_NODES * 64 / 256, 256>>>((const float*)pg1, 64);
    knn_mma_kernel<64><<<128, 256, smem2>>>((const float*)psqn, (int*)pcand);
    rescore_kernel<64><<<N_NODES / 8, 256>>>((const float*)pg1, (const float*)psqn,
                                             (const int*)pcand, (int*)pidx);
    prepw_kernel<<<(64 * 64 + 255) / 256, 256>>>(We2, 64);
    gemm_kernel<0><<<dim3(N_NODES / 64, 1), 256>>>((const float*)pg1, (const float*)pWP, be2,
                                                   (float*)pP, 64, 64);
    gemm_kernel<0><<<dim3(N_NODES / 64, 1), 256>>>((const float*)pg1, (const float*)pWQ, nullptr,
                                                   (float*)pQ, 64, 64);
    maxagg_kernel<<<N_NODES / 4, 256>>>((const float*)pP, (const float*)pQ,
                                        (const int*)pidx, (float*)pg2);

    // classifier
    classifier_kernel<<<N_NODES / 16, 256>>>(Wc, bc, out);
}

// round 6
// speedup vs baseline: 1.2264x; 1.1990x over previous
#include <cuda_runtime.h>
#include <cuda_bf16.h>
#include <cstdint>

#define N_NODES 16384
#define KNN 10
#define CAND 16   // approx candidates kept per query for exact rescoring

// ---------------- scratch (static device allocations; no runtime alloc) ----------------
__device__ float d_E [N_NODES * 192];
__device__ float d_H [N_NODES * 128];
__device__ float d_g1[N_NODES * 64];
__device__ float d_g2[N_NODES * 64];
__device__ float d_P [N_NODES * 64];
__device__ float d_Qm[N_NODES * 64];
__device__ float d_sqn[N_NODES];
__device__ int   d_idx[N_NODES * KNN];
__device__ int   d_cand[N_NODES * CAND];
__device__ float d_WP[128 * 64];
__device__ float d_WQ[128 * 64];
__device__ __nv_bfloat16 d_X2[N_NODES * 128];   // bf16(x), up to 128 cols

// ---------------- PTX helpers (generic sm_80+ features only) ----------------
__device__ __forceinline__ uint32_t smem_u32(const void* p) {
    uint32_t a;
    asm("{ .reg .u64 t; cvta.to.shared.u64 t, %1; cvt.u32.u64 %0, t; }" : "=r"(a) : "l"(p));
    return a;
}
#define CP_ASYNC16(dst, src) \
    asm volatile("cp.async.cg.shared.global [%0], [%1], 16;" :: "r"(dst), "l"(src))
#define CP_COMMIT() asm volatile("cp.async.commit_group;" ::: "memory")
#define CP_WAIT0()  asm volatile("cp.async.wait_group 0;" ::: "memory")

#define LDSM4(r0, r1, r2, r3, addr) \
    asm volatile("ldmatrix.sync.aligned.m8n8.x4.shared.b16 {%0,%1,%2,%3}, [%4];" \
                 : "=r"(r0), "=r"(r1), "=r"(r2), "=r"(r3) : "r"(addr))

#define MMA16816(d, a, b) \
    asm volatile("mma.sync.aligned.m16n8k16.row.col.f32.bf16.bf16.f32 " \
                 "{%0,%1,%2,%3}, {%4,%5,%6,%7}, {%8,%9}, {%0,%1,%2,%3};" \
                 : "+f"((d)[0]), "+f"((d)[1]), "+f"((d)[2]), "+f"((d)[3]) \
                 : "r"((a)[0]), "r"((a)[1]), "r"((a)[2]), "r"((a)[3]), \
                   "r"((b)[0]), "r"((b)[1]))

// ---------------- stage 1: per-modality embeds (relu) -> E[N,192] ----------------
__global__ void embed_kernel(const float* __restrict__ nf, const float* __restrict__ rf,
                             const float* __restrict__ tf,
                             const float* __restrict__ Wb, const float* __restrict__ bb,
                             const float* __restrict__ Wr, const float* __restrict__ br,
                             const float* __restrict__ Wt, const float* __restrict__ bt)
{
    __shared__ float s[136];
    const int n = blockIdx.x;
    const int t = threadIdx.x;
    if (t < 8)                 s[t]            = nf[n * 8 + t];
    if (t >= 64 && t < 128)    s[8 + (t - 64)] = rf[n * 64 + (t - 64)];
    if (t >= 128)              s[72 + (t-128)] = tf[n * 64 + (t - 128)];
    __syncthreads();

    float acc;
    if (t < 64) {
        acc = bb[t];
        #pragma unroll
        for (int e = 0; e < 8; e++) acc = fmaf(s[e], Wb[e * 64 + t], acc);
    } else if (t < 128) {
        const int o = t - 64;
        acc = br[o];
        #pragma unroll 8
        for (int e = 0; e < 64; e++) acc = fmaf(s[8 + e], Wr[e * 64 + o], acc);
    } else {
        const int o = t - 128;
        acc = bt[o];
        #pragma unroll 8
        for (int e = 0; e < 64; e++) acc = fmaf(s[72 + e], Wt[e * 64 + o], acc);
    }
    d_E[n * 192 + t] = fmaxf(acc, 0.0f);
}

// ---------------- generic tiled fp32 GEMM ----------------
template <int ACT>
__global__ __launch_bounds__(256) void gemm_kernel(const float* __restrict__ A,
                                                   const float* __restrict__ W,
                                                   const float* __restrict__ bias,
                                                   float* __restrict__ C,
                                                   int Kd, int Nc)
{
    __shared__ float As[16][64];
    __shared__ float Ws[16][64];
    const int m0 = blockIdx.x * 64;
    const int n0 = blockIdx.y * 64;
    const int tid = threadIdx.x;
    const int tx = tid & 15;
    const int ty = tid >> 4;

    float acc[4][4];
    #pragma unroll
    for (int i = 0; i < 4; i++)
        #pragma unroll
        for (int j = 0; j < 4; j++) acc[i][j] = 0.0f;

    for (int k0 = 0; k0 < Kd; k0 += 16) {
        {
            const int m  = tid >> 2;
            const int kq = (tid & 3) * 4;
            float4 v = *reinterpret_cast<const float4*>(&A[(m0 + m) * Kd + k0 + kq]);
            As[kq + 0][m] = v.x; As[kq + 1][m] = v.y;
            As[kq + 2][m] = v.z; As[kq + 3][m] = v.w;
            const int kk = tid >> 4;
            const int nq = (tid & 15) * 4;
            float4 w = *reinterpret_cast<const float4*>(&W[(k0 + kk) * Nc + n0 + nq]);
            *reinterpret_cast<float4*>(&Ws[kk][nq]) = w;
        }
        __syncthreads();
        #pragma unroll
        for (int k = 0; k < 16; k++) {
            float4 a = *reinterpret_cast<const float4*>(&As[k][ty * 4]);
            float4 b = *reinterpret_cast<const float4*>(&Ws[k][tx * 4]);
            float av[4] = {a.x, a.y, a.z, a.w};
            float bv[4] = {b.x, b.y, b.z, b.w};
            #pragma unroll
            for (int i = 0; i < 4; i++)
                #pragma unroll
                for (int j = 0; j < 4; j++)
                    acc[i][j] = fmaf(av[i], bv[j], acc[i][j]);
        }
        __syncthreads();
    }

    #pragma unroll
    for (int i = 0; i < 4; i++) {
        const int m = m0 + ty * 4 + i;
        #pragma unroll
        for (int j = 0; j < 4; j++) {
            const int n = n0 + tx * 4 + j;
            float v = acc[i][j] + (bias ? bias[n] : 0.0f);
            if (ACT == 2) v = (v > 0.0f) ? v : 0.01f * v;
            C[m * Nc + n] = v;
        }
    }
}

// ---------------- fused: bf16 cast (to d_X2) + exact fp32 squared norms ----------
template <int D>
__global__ void splitsq_kernel(const float* __restrict__ X, float* __restrict__ sqn)
{
    constexpr int PL = D / 32;     // floats per lane
    const int wid  = threadIdx.x >> 5;
    const int lane = threadIdx.x & 31;
    const int n    = blockIdx.x * 8 + wid;

    float v[PL];
    if constexpr (PL == 4) {
        float4 t = *reinterpret_cast<const float4*>(&X[n * D + lane * 4]);
        v[0] = t.x; v[1] = t.y; v[2] = t.z; v[3] = t.w;
    } else {
        float2 t = *reinterpret_cast<const float2*>(&X[n * D + lane * 2]);
        v[0] = t.x; v[1] = t.y;
    }

    float s = 0.0f;
    #pragma unroll
    for (int i = 0; i < PL; i++) s = fmaf(v[i], v[i], s);
    #pragma unroll
    for (int o = 16; o > 0; o >>= 1) s += __shfl_xor_sync(0xFFFFFFFFu, s, o);
    if (lane == 0) sqn[n] = s;

    if constexpr (PL == 4) {
        __nv_bfloat162 h0 = __floats2bfloat162_rn(v[0], v[1]);
        __nv_bfloat162 h1 = __floats2bfloat162_rn(v[2], v[3]);
        *reinterpret_cast<__nv_bfloat162*>(&d_X2[n * D + lane * 4])     = h0;
        *reinterpret_cast<__nv_bfloat162*>(&d_X2[n * D + lane * 4 + 2]) = h1;
    } else {
        __nv_bfloat162 h0 = __floats2bfloat162_rn(v[0], v[1]);
        *reinterpret_cast<__nv_bfloat162*>(&d_X2[n * D + lane * 2]) = h0;
    }
}

// ---------------- top-k insert (generic length) ----------------
template <int M>
__device__ __forceinline__ void topk_insert(float (&topd)[M], int (&topi)[M],
                                            float dd, int ci)
{
    topd[M - 1] = dd; topi[M - 1] = ci;
    #pragma unroll
    for (int z = M - 2; z >= 0; z--) {
        if (topd[z] > topd[z + 1]) {
            float td = topd[z]; topd[z] = topd[z + 1]; topd[z + 1] = td;
            int   ti = topi[z]; topi[z] = topi[z + 1]; topi[z + 1] = ti;
        }
    }
}

// ---------------- approx KNN via mma.sync (single-term bf16 Gram) ----------------
// 128 queries/block, 128-candidate tiles, 8 warps; warp = 64q x 32c patch.
// Emits top-CAND candidate indices per query; exact rescoring picks final top-10.
template <int D>
__global__ __launch_bounds__(256, 1) void knn_mma_kernel(const float* __restrict__ sqn,
                                                         int* __restrict__ outCand)
{
    constexpr int PAD   = 8;
    constexpr int PB    = (D + PAD) * 2;        // smem row pitch in bytes
    constexpr int TILEB = 128 * PB;
    constexpr int CH    = D / 8;                // 16B chunks per row (2D bytes)

    extern __shared__ char smch[];
    char* qt  = smch;
    char* ct0 = smch + TILEB;
    char* ct1 = smch + 2 * TILEB;
    float* dist = reinterpret_cast<float*>(smch + 3 * TILEB);  // 128*132 floats

    __shared__ float s_sqc[2][128];
    __shared__ float s_mg [128 * CAND];
    __shared__ int   s_mgi[128 * CAND];

    const int tid  = threadIdx.x;
    const int wid  = tid >> 5;
    const int lane = tid & 31;
    const int q0   = blockIdx.x * 128;

    const int mrow = (wid & 1) * 64;
    const int ncol = (wid >> 1) * 32;
    const int lrow = lane & 15;
    const int lkof = (lane >> 4) * 16;

    const uint32_t qtu  = smem_u32(qt);
    const uint32_t ctu0 = smem_u32(ct0);
    const uint32_t ctu1 = smem_u32(ct1);
    const uint32_t aBase = qtu + (mrow + lrow) * PB + lkof;
    const uint32_t bOff  = (ncol + lrow) * PB + lkof;

    {
        #pragma unroll 4
        for (int i = tid; i < 128 * CH; i += 256) {
            const int r  = i / CH;
            const int ch = i - r * CH;
            CP_ASYNC16(qtu + r * PB + ch * 16,
                       d_X2 + (size_t)(q0 + r) * D + ch * 8);
        }
        #pragma unroll 4
        for (int i = tid; i < 128 * CH; i += 256) {
            const int r  = i / CH;
            const int ch = i - r * CH;
            CP_ASYNC16(ctu0 + r * PB + ch * 16,
                       d_X2 + (size_t)r * D + ch * 8);
        }
        CP_COMMIT();
        if (tid < 128) s_sqc[0][tid] = sqn[tid];
    }

    float topd[CAND]; int topi[CAND];
    #pragma unroll
    for (int i = 0; i < CAND; i++) { topd[i] = 1e30f; topi[i] = 0; }

    const int qmine = tid & 127;
    const int cbase = (tid >> 7) * 64;

    const int T = N_NODES / 128;
    for (int t = 0; t < T; t++) {
        CP_WAIT0();
        __syncthreads();

        const uint32_t ctu = (t & 1) ? ctu1 : ctu0;
        if (t + 1 < T) {
            const uint32_t ctn = ((t + 1) & 1) ? ctu1 : ctu0;
            const int r0n = (t + 1) * 128;
            #pragma unroll 4
            for (int i = tid; i < 128 * CH; i += 256) {
                const int r  = i / CH;
                const int ch = i - r * CH;
                CP_ASYNC16(ctn + r * PB + ch * 16,
                           d_X2 + (size_t)(r0n + r) * D + ch * 8);
            }
            CP_COMMIT();
            if (tid < 128) s_sqc[(t + 1) & 1][tid] = sqn[r0n + tid];
        }

        float acc[4][4][4];
        #pragma unroll
        for (int mt = 0; mt < 4; mt++)
            #pragma unroll
            for (int nt = 0; nt < 4; nt++)
                #pragma unroll
                for (int r = 0; r < 4; r++) acc[mt][nt][r] = 0.0f;

        const uint32_t bBase = ctu + bOff;
        #pragma unroll
        for (int kc = 0; kc < D; kc += 16) {
            uint32_t a[4][4];
            #pragma unroll
            for (int mt = 0; mt < 4; mt++)
                LDSM4(a[mt][0], a[mt][1], a[mt][2], a[mt][3],
                      aBase + mt * 16 * PB + kc * 2);
            uint32_t b[4][2];
            #pragma unroll
            for (int nb = 0; nb < 2; nb++) {
                uint32_t r0, r1, r2, r3;
                LDSM4(r0, r1, r2, r3, bBase + nb * 16 * PB + kc * 2);
                b[nb * 2][0] = r0; b[nb * 2][1] = r2;
                b[nb * 2 + 1][0] = r1; b[nb * 2 + 1][1] = r3;
            }
            #pragma unroll
            for (int mt = 0; mt < 4; mt++)
                #pragma unroll
                for (int nt = 0; nt < 4; nt++)
                    MMA16816(acc[mt][nt], a[mt], b[nt]);
        }
        __syncthreads();

        const float* sq = s_sqc[t & 1];
        const int c0 = t * 128;

        #pragma unroll
        for (int mt = 0; mt < 4; mt++) {
            const int qA = mrow + mt * 16 + (lane >> 2);
            #pragma unroll
            for (int nt = 0; nt < 4; nt++) {
                const int c = ncol + nt * 8 + (lane & 3) * 2;
                const float s0 = sq[c], s1 = sq[c + 1];
                float2 v0, v1;
                v0.x = fmaf(-2.0f, acc[mt][nt][0], s0);
                v0.y = fmaf(-2.0f, acc[mt][nt][1], s1);
                v1.x = fmaf(-2.0f, acc[mt][nt][2], s0);
                v1.y = fmaf(-2.0f, acc[mt][nt][3], s1);
                const int dq = (q0 + qA) - (c0 + c);
                if (dq ==  0) v0.x = 1e30f;
                if (dq ==  1) v0.y = 1e30f;
                if (dq == -8) v1.x = 1e30f;
                if (dq == -7) v1.y = 1e30f;
                *reinterpret_cast<float2*>(&dist[qA * 132 + c])       = v0;
                *reinterpret_cast<float2*>(&dist[(qA + 8) * 132 + c]) = v1;
            }
        }
        __syncthreads();

        const float* row = &dist[qmine * 132 + cbase];
        #pragma unroll
        for (int cc = 0; cc < 16; cc++) {
            float4 v = *reinterpret_cast<const float4*>(&row[cc * 4]);
            const int ci = c0 + cbase + cc * 4;
            if (v.x < topd[CAND - 1]) topk_insert(topd, topi, v.x, ci + 0);
            if (v.y < topd[CAND - 1]) topk_insert(topd, topi, v.y, ci + 1);
            if (v.z < topd[CAND - 1]) topk_insert(topd, topi, v.z, ci + 2);
            if (v.w < topd[CAND - 1]) topk_insert(topd, topi, v.w, ci + 3);
        }
        __syncthreads();   // scan done before dist overwritten next iter
    }

    // merge the two per-query halves -> exact approx-top-CAND
    if (tid >= 128) {
        const int qq = tid - 128;
        #pragma unroll
        for (int i = 0; i < CAND; i++) {
            s_mg [qq * CAND + i] = topd[i];
            s_mgi[qq * CAND + i] = topi[i];
        }
    }
    __syncthreads();
    if (tid < 128) {
        #pragma unroll
        for (int i = 0; i < CAND; i++) {
            const float dd = s_mg[tid * CAND + i];
            if (dd < topd[CAND - 1]) topk_insert(topd, topi, dd, s_mgi[tid * CAND + i]);
        }
        #pragma unroll
        for (int i = 0; i < CAND; i++) outCand[(q0 + tid) * CAND + i] = topi[i];
    }
}

// ---------------- exact fp32 rescore: top-KNN of CAND candidates per query -------
template <int D>
__global__ void rescore_kernel(const float* __restrict__ X, const float* __restrict__ sqn,
                               const int* __restrict__ cand, int* __restrict__ outIdx)
{
    constexpr int PL = D / 32;
    const int wid  = threadIdx.x >> 5;
    const int lane = threadIdx.x & 31;
    const int q    = blockIdx.x * 8 + wid;

    float xq[PL];
    #pragma unroll
    for (int i = 0; i < PL; i++) xq[i] = X[q * D + i * 32 + lane];

    float topd[KNN]; int topi[KNN];
    #pragma unroll
    for (int i = 0; i < KNN; i++) { topd[i] = 1e30f; topi[i] = 0; }

    #pragma unroll
    for (int j = 0; j < CAND; j++) {
        const int c = cand[q * CAND + j];
        float dot = 0.0f;
        #pragma unroll
        for (int i = 0; i < PL; i++) dot = fmaf(xq[i], X[c * D + i * 32 + lane], dot);
        #pragma unroll
        for (int o = 16; o > 0; o >>= 1) dot += __shfl_xor_sync(0xFFFFFFFFu, dot, o);
        const float dd = fmaf(-2.0f, dot, sqn[c]);
        if (dd < topd[KNN - 1]) topk_insert(topd, topi, dd, c);
    }
    if (lane == 0) {
        #pragma unroll
        for (int i = 0; i < KNN; i++) outIdx[q * KNN + i] = topi[i];
    }
}

// ---------------- EdgeConv weight split: WP = Wa - Wb, WQ = Wb ----------------
__global__ void prepw_kernel(const float* __restrict__ We, int D)
{
    const int i = blockIdx.x * 256 + threadIdx.x;
    if (i < D * 64) {
        const float b = We[D * 64 + i];
        d_WQ[i] = b;
        d_WP[i] = We[i] - b;
    }
}

// ---------------- EdgeConv aggregation ----------------
__global__ void maxagg_kernel(const float* __restrict__ P, const float* __restrict__ Q,
                              const int* __restrict__ idx, float* __restrict__ g)
{
    const int tid = threadIdx.x;
    const int n = blockIdx.x * 4 + (tid >> 6);
    const int o = tid & 63;
    const float p = P[n * 64 + o];
    float m = -1e30f;
    #pragma unroll
    for (int kk = 0; kk < KNN; kk++) {
        const int j = idx[n * KNN + kk];
        float v = p + Q[j * 64 + o];
        v = (v > 0.0f) ? v : 0.01f * v;
        m = fmaxf(m, v);
    }
    g[n * 64 + o] = m;
}

// ---------------- classifier ----------------
__global__ void classifier_kernel(const float* __restrict__ Wc, const float* __restrict__ bc,
                                  float* __restrict__ out)
{
    const int tid = threadIdx.x;
    const int n = blockIdx.x * 16 + (tid >> 4);
    const int c = tid & 15;
    float acc = bc[c];
    const float* g1r = d_g1 + n * 64;
    const float* g2r = d_g2 + n * 64;
    #pragma unroll 8
    for (int o = 0; o < 64; o++) {
        acc = fmaf(g1r[o], Wc[o * 16 + c], acc);
        acc = fmaf(g2r[o], Wc[(64 + o) * 16 + c], acc);
    }
    out[n * 16 + c] = acc;
}

// ---------------- launch ----------------
extern "C" void kernel_launch(void* const* d_in, const int* in_sizes, int n_in,
                              void* d_out, int out_size)
{
    const float* node_feat = (const float*)d_in[0];
    const float* rf_feat   = (const float*)d_in[1];
    const float* txp_feat  = (const float*)d_in[2];
    const float* Wb  = (const float*)d_in[3];
    const float* bb  = (const float*)d_in[4];
    const float* Wr  = (const float*)d_in[5];
    const float* br  = (const float*)d_in[6];
    const float* Wt  = (const float*)d_in[7];
    const float* bt  = (const float*)d_in[8];
    const float* Wf  = (const float*)d_in[9];
    const float* bf  = (const float*)d_in[10];
    const float* We1 = (const float*)d_in[11];
    const float* be1 = (const float*)d_in[12];
    const float* We2 = (const float*)d_in[13];
    const float* be2 = (const float*)d_in[14];
    const float* Wc  = (const float*)d_in[15];
    const float* bc  = (const float*)d_in[16];
    float* out = (float*)d_out;

    void *pE, *pH, *pg1, *pg2, *pP, *pQ, *psqn, *pidx, *pcand, *pWP, *pWQ;
    cudaGetSymbolAddress(&pE,    d_E);
    cudaGetSymbolAddress(&pH,    d_H);
    cudaGetSymbolAddress(&pg1,   d_g1);
    cudaGetSymbolAddress(&pg2,   d_g2);
    cudaGetSymbolAddress(&pP,    d_P);
    cudaGetSymbolAddress(&pQ,    d_Qm);
    cudaGetSymbolAddress(&psqn,  d_sqn);
    cudaGetSymbolAddress(&pidx,  d_idx);
    cudaGetSymbolAddress(&pcand, d_cand);
    cudaGetSymbolAddress(&pWP,   d_WP);
    cudaGetSymbolAddress(&pWQ,   d_WQ);

    // D=128: 3 tiles x 34816B + dist 67584B = 172032B dynamic
    // D=64 : 3 tiles x 18432B + dist 67584B = 122880B dynamic
    const int smem1 = 3 * 128 * 272 + 128 * 132 * 4;
    const int smem2 = 3 * 128 * 144 + 128 * 132 * 4;
    cudaFuncSetAttribute(knn_mma_kernel<128>, cudaFuncAttributeMaxDynamicSharedMemorySize, smem1);
    cudaFuncSetAttribute(knn_mma_kernel<64>,  cudaFuncAttributeMaxDynamicSharedMemorySize, smem2);

    // stage 1: embeds + fusion   (launch order puts knn<128> at profiled slot #4)
    embed_kernel<<<N_NODES, 192>>>(node_feat, rf_feat, txp_feat, Wb, bb, Wr, br, Wt, bt);
    gemm_kernel<2><<<dim3(N_NODES / 64, 2), 256>>>((const float*)pE, Wf, bf, (float*)pH, 192, 128);

    // EdgeConv 1
    splitsq_kernel<128><<<N_NODES / 8, 256>>>((const float*)pH, (float*)psqn);
    knn_mma_kernel<128><<<128, 256, smem1>>>((const float*)psqn, (int*)pcand);
    rescore_kernel<128><<<N_NODES / 8, 256>>>((const float*)pH, (const float*)psqn,
                                              (const int*)pcand, (int*)pidx);
    prepw_kernel<<<(128 * 64 + 255) / 256, 256>>>(We1, 128);
    gemm_kernel<0><<<dim3(N_NODES / 64, 1), 256>>>((const float*)pH, (const float*)pWP, be1,
                                                   (float*)pP, 128, 64);
    gemm_kernel<0><<<dim3(N_NODES / 64, 1), 256>>>((const float*)pH, (const float*)pWQ, nullptr,
                                                   (float*)pQ, 128, 64);
    maxagg_kernel<<<N_NODES / 4, 256>>>((const float*)pP, (const float*)pQ,
                                        (const int*)pidx, (float*)pg1);

    // EdgeConv 2
    splitsq_kernel<64><<<N_NODES / 8, 256>>>((const float*)pg1, (float*)psqn);
    knn_mma_kernel<64><<<128, 256, smem2>>>((const float*)psqn, (int*)pcand);
    rescore_kernel<64><<<N_NODES / 8, 256>>>((const float*)pg1, (const float*)psqn,
                                             (const int*)pcand, (int*)pidx);
    prepw_kernel<<<(64 * 64 + 255) / 256, 256>>>(We2, 64);
    gemm_kernel<0><<<dim3(N_NODES / 64, 1), 256>>>((const float*)pg1, (const float*)pWP, be2,
                                                   (float*)pP, 64, 64);
    gemm_kernel<0><<<dim3(N_NODES / 64, 1), 256>>>((const float*)pg1, (const float*)pWQ, nullptr,
                                                   (float*)pQ, 64, 64);
    maxagg_kernel<<<N_NODES / 4, 256>>>((const float*)pP, (const float*)pQ,
                                        (const int*)pidx, (float*)pg2);

    // classifier
    classifier_kernel<<<N_NODES / 16, 256>>>(Wc, bc, out);
}

// round 7
// speedup vs baseline: 2.1971x; 1.7915x over previous
#include <cuda_runtime.h>
#include <cuda_bf16.h>
#include <cstdint>

#define N_NODES 16384
#define KNN 10
#define CAND 16   // approx candidates kept per query for exact rescoring

// ---------------- scratch (static device allocations; no runtime alloc) ----------------
__device__ float d_E [N_NODES * 192];
__device__ float d_H [N_NODES * 128];
__device__ float d_g1[N_NODES * 64];
__device__ float d_g2[N_NODES * 64];
__device__ float d_P [N_NODES * 64];
__device__ float d_Qm[N_NODES * 64];
__device__ float d_sqn[N_NODES];
__device__ int   d_idx[N_NODES * KNN];
__device__ int   d_cand[N_NODES * CAND];
__device__ float d_WP[128 * 64];
__device__ float d_WQ[128 * 64];
__device__ __nv_bfloat16 d_X2[N_NODES * 128];   // bf16(x), up to 128 cols

// ---------------- PTX helpers (generic sm_80+ features only) ----------------
__device__ __forceinline__ uint32_t smem_u32(const void* p) {
    uint32_t a;
    asm("{ .reg .u64 t; cvta.to.shared.u64 t, %1; cvt.u32.u64 %0, t; }" : "=r"(a) : "l"(p));
    return a;
}
#define CP_ASYNC16(dst, src) \
    asm volatile("cp.async.cg.shared.global [%0], [%1], 16;" :: "r"(dst), "l"(src))
#define CP_COMMIT() asm volatile("cp.async.commit_group;" ::: "memory")
#define CP_WAIT0()  asm volatile("cp.async.wait_group 0;" ::: "memory")

#define LDSM4(r0, r1, r2, r3, addr) \
    asm volatile("ldmatrix.sync.aligned.m8n8.x4.shared.b16 {%0,%1,%2,%3}, [%4];" \
                 : "=r"(r0), "=r"(r1), "=r"(r2), "=r"(r3) : "r"(addr))

#define MMA16816(d, a, b) \
    asm volatile("mma.sync.aligned.m16n8k16.row.col.f32.bf16.bf16.f32 " \
                 "{%0,%1,%2,%3}, {%4,%5,%6,%7}, {%8,%9}, {%0,%1,%2,%3};" \
                 : "+f"((d)[0]), "+f"((d)[1]), "+f"((d)[2]), "+f"((d)[3]) \
                 : "r"((a)[0]), "r"((a)[1]), "r"((a)[2]), "r"((a)[3]), \
                   "r"((b)[0]), "r"((b)[1]))

// ---------------- stage 1: per-modality embeds (relu) -> E[N,192] ----------------
__global__ void embed_kernel(const float* __restrict__ nf, const float* __restrict__ rf,
                             const float* __restrict__ tf,
                             const float* __restrict__ Wb, const float* __restrict__ bb,
                             const float* __restrict__ Wr, const float* __restrict__ br,
                             const float* __restrict__ Wt, const float* __restrict__ bt)
{
    __shared__ float s[136];
    const int n = blockIdx.x;
    const int t = threadIdx.x;
    if (t < 8)                 s[t]            = nf[n * 8 + t];
    if (t >= 64 && t < 128)    s[8 + (t - 64)] = rf[n * 64 + (t - 64)];
    if (t >= 128)              s[72 + (t-128)] = tf[n * 64 + (t - 128)];
    __syncthreads();

    float acc;
    if (t < 64) {
        acc = bb[t];
        #pragma unroll
        for (int e = 0; e < 8; e++) acc = fmaf(s[e], Wb[e * 64 + t], acc);
    } else if (t < 128) {
        const int o = t - 64;
        acc = br[o];
        #pragma unroll 8
        for (int e = 0; e < 64; e++) acc = fmaf(s[8 + e], Wr[e * 64 + o], acc);
    } else {
        const int o = t - 128;
        acc = bt[o];
        #pragma unroll 8
        for (int e = 0; e < 64; e++) acc = fmaf(s[72 + e], Wt[e * 64 + o], acc);
    }
    d_E[n * 192 + t] = fmaxf(acc, 0.0f);
}

// ---------------- generic tiled fp32 GEMM ----------------
template <int ACT>
__global__ __launch_bounds__(256) void gemm_kernel(const float* __restrict__ A,
                                                   const float* __restrict__ W,
                                                   const float* __restrict__ bias,
                                                   float* __restrict__ C,
                                                   int Kd, int Nc)
{
    __shared__ float As[16][64];
    __shared__ float Ws[16][64];
    const int m0 = blockIdx.x * 64;
    const int n0 = blockIdx.y * 64;
    const int tid = threadIdx.x;
    const int tx = tid & 15;
    const int ty = tid >> 4;

    float acc[4][4];
    #pragma unroll
    for (int i = 0; i < 4; i++)
        #pragma unroll
        for (int j = 0; j < 4; j++) acc[i][j] = 0.0f;

    for (int k0 = 0; k0 < Kd; k0 += 16) {
        {
            const int m  = tid >> 2;
            const int kq = (tid & 3) * 4;
            float4 v = *reinterpret_cast<const float4*>(&A[(m0 + m) * Kd + k0 + kq]);
            As[kq + 0][m] = v.x; As[kq + 1][m] = v.y;
            As[kq + 2][m] = v.z; As[kq + 3][m] = v.w;
            const int kk = tid >> 4;
            const int nq = (tid & 15) * 4;
            float4 w = *reinterpret_cast<const float4*>(&W[(k0 + kk) * Nc + n0 + nq]);
            *reinterpret_cast<float4*>(&Ws[kk][nq]) = w;
        }
        __syncthreads();
        #pragma unroll
        for (int k = 0; k < 16; k++) {
            float4 a = *reinterpret_cast<const float4*>(&As[k][ty * 4]);
            float4 b = *reinterpret_cast<const float4*>(&Ws[k][tx * 4]);
            float av[4] = {a.x, a.y, a.z, a.w};
            float bv[4] = {b.x, b.y, b.z, b.w};
            #pragma unroll
            for (int i = 0; i < 4; i++)
                #pragma unroll
                for (int j = 0; j < 4; j++)
                    acc[i][j] = fmaf(av[i], bv[j], acc[i][j]);
        }
        __syncthreads();
    }

    #pragma unroll
    for (int i = 0; i < 4; i++) {
        const int m = m0 + ty * 4 + i;
        #pragma unroll
        for (int j = 0; j < 4; j++) {
            const int n = n0 + tx * 4 + j;
            float v = acc[i][j] + (bias ? bias[n] : 0.0f);
            if (ACT == 2) v = (v > 0.0f) ? v : 0.01f * v;
            C[m * Nc + n] = v;
        }
    }
}

// ---------------- fused: bf16 cast (to d_X2) + exact fp32 squared norms ----------
template <int D>
__global__ void splitsq_kernel(const float* __restrict__ X, float* __restrict__ sqn)
{
    constexpr int PL = D / 32;
    const int wid  = threadIdx.x >> 5;
    const int lane = threadIdx.x & 31;
    const int n    = blockIdx.x * 8 + wid;

    float v[PL];
    if constexpr (PL == 4) {
        float4 t = *reinterpret_cast<const float4*>(&X[n * D + lane * 4]);
        v[0] = t.x; v[1] = t.y; v[2] = t.z; v[3] = t.w;
    } else {
        float2 t = *reinterpret_cast<const float2*>(&X[n * D + lane * 2]);
        v[0] = t.x; v[1] = t.y;
    }

    float s = 0.0f;
    #pragma unroll
    for (int i = 0; i < PL; i++) s = fmaf(v[i], v[i], s);
    #pragma unroll
    for (int o = 16; o > 0; o >>= 1) s += __shfl_xor_sync(0xFFFFFFFFu, s, o);
    if (lane == 0) sqn[n] = s;

    if constexpr (PL == 4) {
        __nv_bfloat162 h0 = __floats2bfloat162_rn(v[0], v[1]);
        __nv_bfloat162 h1 = __floats2bfloat162_rn(v[2], v[3]);
        *reinterpret_cast<__nv_bfloat162*>(&d_X2[n * D + lane * 4])     = h0;
        *reinterpret_cast<__nv_bfloat162*>(&d_X2[n * D + lane * 4 + 2]) = h1;
    } else {
        __nv_bfloat162 h0 = __floats2bfloat162_rn(v[0], v[1]);
        *reinterpret_cast<__nv_bfloat162*>(&d_X2[n * D + lane * 2]) = h0;
    }
}

// ---------------- top-k insert (generic length) ----------------
template <int M>
__device__ __forceinline__ void topk_insert(float (&topd)[M], int (&topi)[M],
                                            float dd, int ci)
{
    topd[M - 1] = dd; topi[M - 1] = ci;
    #pragma unroll
    for (int z = M - 2; z >= 0; z--) {
        if (topd[z] > topd[z + 1]) {
            float td = topd[z]; topd[z] = topd[z + 1]; topd[z + 1] = td;
            int   ti = topi[z]; topi[z] = topi[z + 1]; topi[z + 1] = ti;
        }
    }
}

// ---------------- approx KNN via mma.sync (single-term bf16 Gram), 512 threads ----
// 128 queries/block, 128-candidate tiles, 16 warps; warp = 32q x 32c patch.
// Scan: 4 threads per query x 32 candidates. Emits top-CAND per query.
template <int D>
__global__ __launch_bounds__(512, 1) void knn_mma_kernel(const float* __restrict__ sqn,
                                                         int* __restrict__ outCand)
{
    constexpr int PAD   = 8;
    constexpr int PB    = (D + PAD) * 2;        // smem row pitch in bytes
    constexpr int TILEB = 128 * PB;
    constexpr int CH    = D / 8;                // 16B chunks per row

    extern __shared__ char smch[];
    char* qt  = smch;
    char* ct0 = smch + TILEB;
    char* ct1 = smch + 2 * TILEB;
    float* dist = reinterpret_cast<float*>(smch + 3 * TILEB);  // 128*132 floats

    __shared__ float s_sqc[2][128];
    __shared__ float s_mg [128 * CAND];
    __shared__ int   s_mgi[128 * CAND];

    const int tid  = threadIdx.x;
    const int wid  = tid >> 5;
    const int lane = tid & 31;
    const int q0   = blockIdx.x * 128;

    const int mrow = (wid & 3) * 32;            // warp's query-row base
    const int ncol = (wid >> 2) * 32;           // warp's candidate-col base
    const int lrow = lane & 15;
    const int lkof = (lane >> 4) * 16;

    const uint32_t qtu  = smem_u32(qt);
    const uint32_t ctu0 = smem_u32(ct0);
    const uint32_t ctu1 = smem_u32(ct1);
    const uint32_t aBase = qtu + (mrow + lrow) * PB + lkof;
    const uint32_t bOff  = (ncol + lrow) * PB + lkof;

    {
        #pragma unroll
        for (int i = tid; i < 128 * CH; i += 512) {
            const int r  = i / CH;
            const int ch = i - r * CH;
            CP_ASYNC16(qtu + r * PB + ch * 16,
                       d_X2 + (size_t)(q0 + r) * D + ch * 8);
        }
        #pragma unroll
        for (int i = tid; i < 128 * CH; i += 512) {
            const int r  = i / CH;
            const int ch = i - r * CH;
            CP_ASYNC16(ctu0 + r * PB + ch * 16,
                       d_X2 + (size_t)r * D + ch * 8);
        }
        CP_COMMIT();
        if (tid < 128) s_sqc[0][tid] = sqn[tid];
    }

    float topd[CAND]; int topi[CAND];
    #pragma unroll
    for (int i = 0; i < CAND; i++) { topd[i] = 1e30f; topi[i] = 0; }

    const int qmine = tid & 127;     // query owned for scanning
    const int grp   = tid >> 7;      // 0..3: quarter of the candidate tile
    const int cbase = grp * 32;

    const int T = N_NODES / 128;
    for (int t = 0; t < T; t++) {
        CP_WAIT0();
        __syncthreads();             // tile t resident; prior scan complete

        const uint32_t ctu = (t & 1) ? ctu1 : ctu0;
        if (t + 1 < T) {
            const uint32_t ctn = ((t + 1) & 1) ? ctu1 : ctu0;
            const int r0n = (t + 1) * 128;
            #pragma unroll
            for (int i = tid; i < 128 * CH; i += 512) {
                const int r  = i / CH;
                const int ch = i - r * CH;
                CP_ASYNC16(ctn + r * PB + ch * 16,
                           d_X2 + (size_t)(r0n + r) * D + ch * 8);
            }
            CP_COMMIT();
            if (tid < 128) s_sqc[(t + 1) & 1][tid] = sqn[r0n + tid];
        }

        // ---- Gram: warp 32q x 32c, m16n8k16 atoms ----
        float acc[2][4][4];
        #pragma unroll
        for (int mt = 0; mt < 2; mt++)
            #pragma unroll
            for (int nt = 0; nt < 4; nt++)
                #pragma unroll
                for (int r = 0; r < 4; r++) acc[mt][nt][r] = 0.0f;

        const uint32_t bBase = ctu + bOff;
        #pragma unroll
        for (int kc = 0; kc < D; kc += 16) {
            uint32_t a[2][4];
            #pragma unroll
            for (int mt = 0; mt < 2; mt++)
                LDSM4(a[mt][0], a[mt][1], a[mt][2], a[mt][3],
                      aBase + mt * 16 * PB + kc * 2);
            uint32_t b[4][2];
            #pragma unroll
            for (int nb = 0; nb < 2; nb++) {
                uint32_t r0, r1, r2, r3;
                LDSM4(r0, r1, r2, r3, bBase + nb * 16 * PB + kc * 2);
                b[nb * 2][0] = r0; b[nb * 2][1] = r2;
                b[nb * 2 + 1][0] = r1; b[nb * 2 + 1][1] = r3;
            }
            #pragma unroll
            for (int mt = 0; mt < 2; mt++)
                #pragma unroll
                for (int nt = 0; nt < 4; nt++)
                    MMA16816(acc[mt][nt], a[mt], b[nt]);
        }
        __syncthreads();             // mma reads done before dist write

        const float* sq = s_sqc[t & 1];
        const int c0 = t * 128;

        #pragma unroll
        for (int mt = 0; mt < 2; mt++) {
            const int qA = mrow + mt * 16 + (lane >> 2);
            #pragma unroll
            for (int nt = 0; nt < 4; nt++) {
                const int c = ncol + nt * 8 + (lane & 3) * 2;
                const float s0 = sq[c], s1 = sq[c + 1];
                float2 v0, v1;
                v0.x = fmaf(-2.0f, acc[mt][nt][0], s0);
                v0.y = fmaf(-2.0f, acc[mt][nt][1], s1);
                v1.x = fmaf(-2.0f, acc[mt][nt][2], s0);
                v1.y = fmaf(-2.0f, acc[mt][nt][3], s1);
                const int dq = (q0 + qA) - (c0 + c);
                if (dq ==  0) v0.x = 1e30f;
                if (dq ==  1) v0.y = 1e30f;
                if (dq == -8) v1.x = 1e30f;
                if (dq == -7) v1.y = 1e30f;
                *reinterpret_cast<float2*>(&dist[qA * 132 + c])       = v0;
                *reinterpret_cast<float2*>(&dist[(qA + 8) * 132 + c]) = v1;
            }
        }
        __syncthreads();

        // ---- scan: 4 threads per query, 32 candidates each ----
        const float* row = &dist[qmine * 132 + cbase];
        #pragma unroll
        for (int cc = 0; cc < 8; cc++) {
            float4 v = *reinterpret_cast<const float4*>(&row[cc * 4]);
            const int ci = c0 + cbase + cc * 4;
            if (v.x < topd[CAND - 1]) topk_insert(topd, topi, v.x, ci + 0);
            if (v.y < topd[CAND - 1]) topk_insert(topd, topi, v.y, ci + 1);
            if (v.z < topd[CAND - 1]) topk_insert(topd, topi, v.z, ci + 2);
            if (v.w < topd[CAND - 1]) topk_insert(topd, topi, v.w, ci + 3);
        }
    }

    // ---- merge the four per-query quarters (3 rounds through one buffer) ----
    #pragma unroll 1
    for (int s = 1; s < 4; s++) {
        __syncthreads();
        if (grp == s) {
            #pragma unroll
            for (int i = 0; i < CAND; i++) {
                s_mg [qmine * CAND + i] = topd[i];
                s_mgi[qmine * CAND + i] = topi[i];
            }
        }
        __syncthreads();
        if (grp == 0) {
            #pragma unroll
            for (int i = 0; i < CAND; i++) {
                const float dd = s_mg[qmine * CAND + i];
                if (dd < topd[CAND - 1]) topk_insert(topd, topi, dd, s_mgi[qmine * CAND + i]);
            }
        }
    }
    if (grp == 0) {
        #pragma unroll
        for (int i = 0; i < CAND; i++) outCand[(q0 + qmine) * CAND + i] = topi[i];
    }
}

// ---------------- exact fp32 rescore: top-KNN of CAND candidates per query -------
template <int D>
__global__ void rescore_kernel(const float* __restrict__ X, const float* __restrict__ sqn,
                               const int* __restrict__ cand, int* __restrict__ outIdx)
{
    constexpr int PL = D / 32;
    const int wid  = threadIdx.x >> 5;
    const int lane = threadIdx.x & 31;
    const int q    = blockIdx.x * 8 + wid;

    float xq[PL];
    #pragma unroll
    for (int i = 0; i < PL; i++) xq[i] = X[q * D + i * 32 + lane];

    float topd[KNN]; int topi[KNN];
    #pragma unroll
    for (int i = 0; i < KNN; i++) { topd[i] = 1e30f; topi[i] = 0; }

    #pragma unroll
    for (int j = 0; j < CAND; j++) {
        const int c = cand[q * CAND + j];
        float dot = 0.0f;
        #pragma unroll
        for (int i = 0; i < PL; i++) dot = fmaf(xq[i], X[c * D + i * 32 + lane], dot);
        #pragma unroll
        for (int o = 16; o > 0; o >>= 1) dot += __shfl_xor_sync(0xFFFFFFFFu, dot, o);
        const float dd = fmaf(-2.0f, dot, sqn[c]);
        if (dd < topd[KNN - 1]) topk_insert(topd, topi, dd, c);
    }
    if (lane == 0) {
        #pragma unroll
        for (int i = 0; i < KNN; i++) outIdx[q * KNN + i] = topi[i];
    }
}

// ---------------- EdgeConv weight split: WP = Wa - Wb, WQ = Wb ----------------
__global__ void prepw_kernel(const float* __restrict__ We, int D)
{
    const int i = blockIdx.x * 256 + threadIdx.x;
    if (i < D * 64) {
        const float b = We[D * 64 + i];
        d_WQ[i] = b;
        d_WP[i] = We[i] - b;
    }
}

// ---------------- EdgeConv aggregation ----------------
__global__ void maxagg_kernel(const float* __restrict__ P, const float* __restrict__ Q,
                              const int* __restrict__ idx, float* __restrict__ g)
{
    const int tid = threadIdx.x;
    const int n = blockIdx.x * 4 + (tid >> 6);
    const int o = tid & 63;
    const float p = P[n * 64 + o];
    float m = -1e30f;
    #pragma unroll
    for (int kk = 0; kk < KNN; kk++) {
        const int j = idx[n * KNN + kk];
        float v = p + Q[j * 64 + o];
        v = (v > 0.0f) ? v : 0.01f * v;
        m = fmaxf(m, v);
    }
    g[n * 64 + o] = m;
}

// ---------------- classifier ----------------
__global__ void classifier_kernel(const float* __restrict__ Wc, const float* __restrict__ bc,
                                  float* __restrict__ out)
{
    const int tid = threadIdx.x;
    const int n = blockIdx.x * 16 + (tid >> 4);
    const int c = tid & 15;
    float acc = bc[c];
    const float* g1r = d_g1 + n * 64;
    const float* g2r = d_g2 + n * 64;
    #pragma unroll 8
    for (int o = 0; o < 64; o++) {
        acc = fmaf(g1r[o], Wc[o * 16 + c], acc);
        acc = fmaf(g2r[o], Wc[(64 + o) * 16 + c], acc);
    }
    out[n * 16 + c] = acc;
}

// ---------------- launch ----------------
extern "C" void kernel_launch(void* const* d_in, const int* in_sizes, int n_in,
                              void* d_out, int out_size)
{
    const float* node_feat = (const float*)d_in[0];
    const float* rf_feat   = (const float*)d_in[1];
    const float* txp_feat  = (const float*)d_in[2];
    const float* Wb  = (const float*)d_in[3];
    const float* bb  = (const float*)d_in[4];
    const float* Wr  = (const float*)d_in[5];
    const float* br  = (const float*)d_in[6];
    const float* Wt  = (const float*)d_in[7];
    const float* bt  = (const float*)d_in[8];
    const float* Wf  = (const float*)d_in[9];
    const float* bf  = (const float*)d_in[10];
    const float* We1 = (const float*)d_in[11];
    const float* be1 = (const float*)d_in[12];
    const float* We2 = (const float*)d_in[13];
    const float* be2 = (const float*)d_in[14];
    const float* Wc  = (const float*)d_in[15];
    const float* bc  = (const float*)d_in[16];
    float* out = (float*)d_out;

    void *pE, *pH, *pg1, *pg2, *pP, *pQ, *psqn, *pidx, *pcand, *pWP, *pWQ;
    cudaGetSymbolAddress(&pE,    d_E);
    cudaGetSymbolAddress(&pH,    d_H);
    cudaGetSymbolAddress(&pg1,   d_g1);
    cudaGetSymbolAddress(&pg2,   d_g2);
    cudaGetSymbolAddress(&pP,    d_P);
    cudaGetSymbolAddress(&pQ,    d_Qm);
    cudaGetSymbolAddress(&psqn,  d_sqn);
    cudaGetSymbolAddress(&pidx,  d_idx);
    cudaGetSymbolAddress(&pcand, d_cand);
    cudaGetSymbolAddress(&pWP,   d_WP);
    cudaGetSymbolAddress(&pWQ,   d_WQ);

    // D=128: 3 tiles x 34816B + dist 67584B = 172032B dynamic
    // D=64 : 3 tiles x 18432B + dist 67584B = 122880B dynamic
    const int smem1 = 3 * 128 * 272 + 128 * 132 * 4;
    const int smem2 = 3 * 128 * 144 + 128 * 132 * 4;
    cudaFuncSetAttribute(knn_mma_kernel<128>, cudaFuncAttributeMaxDynamicSharedMemorySize, smem1);
    cudaFuncSetAttribute(knn_mma_kernel<64>,  cudaFuncAttributeMaxDynamicSharedMemorySize, smem2);

    // stage 1: embeds + fusion   (launch order keeps knn<128> at profiled slot #4)
    embed_kernel<<<N_NODES, 192>>>(node_feat, rf_feat, txp_feat, Wb, bb, Wr, br, Wt, bt);
    gemm_kernel<2><<<dim3(N_NODES / 64, 2), 256>>>((const float*)pE, Wf, bf, (float*)pH, 192, 128);

    // EdgeConv 1
    splitsq_kernel<128><<<N_NODES / 8, 256>>>((const float*)pH, (float*)psqn);
    knn_mma_kernel<128><<<128, 512, smem1>>>((const float*)psqn, (int*)pcand);
    rescore_kernel<128><<<N_NODES / 8, 256>>>((const float*)pH, (const float*)psqn,
                                              (const int*)pcand, (int*)pidx);
    prepw_kernel<<<(128 * 64 + 255) / 256, 256>>>(We1, 128);
    gemm_kernel<0><<<dim3(N_NODES / 64, 1), 256>>>((const float*)pH, (const float*)pWP, be1,
                                                   (float*)pP, 128, 64);
    gemm_kernel<0><<<dim3(N_NODES / 64, 1), 256>>>((const float*)pH, (const float*)pWQ, nullptr,
                                                   (float*)pQ, 128, 64);
    maxagg_kernel<<<N_NODES / 4, 256>>>((const float*)pP, (const float*)pQ,
                                        (const int*)pidx, (float*)pg1);

    // EdgeConv 2
    splitsq_kernel<64><<<N_NODES / 8, 256>>>((const float*)pg1, (float*)psqn);
    knn_mma_kernel<64><<<128, 512, smem2>>>((const float*)psqn, (int*)pcand);
    rescore_kernel<64><<<N_NODES / 8, 256>>>((const float*)pg1, (const float*)psqn,
                                             (const int*)pcand, (int*)pidx);
    prepw_kernel<<<(64 * 64 + 255) / 256, 256>>>(We2, 64);
    gemm_kernel<0><<<dim3(N_NODES / 64, 1), 256>>>((const float*)pg1, (const float*)pWP, be2,
                                                   (float*)pP, 64, 64);
    gemm_kernel<0><<<dim3(N_NODES / 64, 1), 256>>>((const float*)pg1, (const float*)pWQ, nullptr,
                                                   (float*)pQ, 64, 64);
    maxagg_kernel<<<N_NODES / 4, 256>>>((const float*)pP, (const float*)pQ,
                                        (const int*)pidx, (float*)pg2);

    // classifier
    classifier_kernel<<<N_NODES / 16, 256>>>(Wc, bc, out);
}

// round 9
// speedup vs baseline: 2.2430x; 1.0209x over previous
#include <cuda_runtime.h>
#include <cuda_bf16.h>
#include <cstdint>

#define N_NODES 16384
#define KNN 10
#define CAND 16   // approx candidates kept per query for exact rescoring

// ---------------- scratch (static device allocations; no runtime alloc) ----------------
__device__ float d_E [N_NODES * 192];
__device__ float d_H [N_NODES * 128];
__device__ float d_g1[N_NODES * 64];
__device__ float d_g2[N_NODES * 64];
__device__ float d_P [N_NODES * 64];
__device__ float d_Qm[N_NODES * 64];
__device__ float d_sqn[N_NODES];
__device__ int   d_idx[N_NODES * KNN];
__device__ int   d_cand[N_NODES * CAND];
__device__ float d_WP[128 * 64];
__device__ float d_WQ[128 * 64];
__device__ __nv_bfloat16 d_X2[N_NODES * 128];   // bf16(x), up to 128 cols

// ---------------- PTX helpers (generic sm_80+ features only) ----------------
__device__ __forceinline__ uint32_t smem_u32(const void* p) {
    uint32_t a;
    asm("{ .reg .u64 t; cvta.to.shared.u64 t, %1; cvt.u32.u64 %0, t; }" : "=r"(a) : "l"(p));
    return a;
}
#define CP_ASYNC16(dst, src) \
    asm volatile("cp.async.cg.shared.global [%0], [%1], 16;" :: "r"(dst), "l"(src))
#define CP_COMMIT() asm volatile("cp.async.commit_group;" ::: "memory")
#define CP_WAIT0()  asm volatile("cp.async.wait_group 0;" ::: "memory")

#define LDSM4(r0, r1, r2, r3, addr) \
    asm volatile("ldmatrix.sync.aligned.m8n8.x4.shared.b16 {%0,%1,%2,%3}, [%4];" \
                 : "=r"(r0), "=r"(r1), "=r"(r2), "=r"(r3) : "r"(addr))

#define MMA16816(d, a, b) \
    asm volatile("mma.sync.aligned.m16n8k16.row.col.f32.bf16.bf16.f32 " \
                 "{%0,%1,%2,%3}, {%4,%5,%6,%7}, {%8,%9}, {%0,%1,%2,%3};" \
                 : "+f"((d)[0]), "+f"((d)[1]), "+f"((d)[2]), "+f"((d)[3]) \
                 : "r"((a)[0]), "r"((a)[1]), "r"((a)[2]), "r"((a)[3]), \
                   "r"((b)[0]), "r"((b)[1]))

// ---------------- stage 1: per-modality embeds (relu) -> E[N,192] ----------------
__global__ void embed_kernel(const float* __restrict__ nf, const float* __restrict__ rf,
                             const float* __restrict__ tf,
                             const float* __restrict__ Wb, const float* __restrict__ bb,
                             const float* __restrict__ Wr, const float* __restrict__ br,
                             const float* __restrict__ Wt, const float* __restrict__ bt)
{
    __shared__ float s[136];
    const int n = blockIdx.x;
    const int t = threadIdx.x;
    if (t < 8)                 s[t]            = nf[n * 8 + t];
    if (t >= 64 && t < 128)    s[8 + (t - 64)] = rf[n * 64 + (t - 64)];
    if (t >= 128)              s[72 + (t-128)] = tf[n * 64 + (t - 128)];
    __syncthreads();

    float acc;
    if (t < 64) {
        acc = bb[t];
        #pragma unroll
        for (int e = 0; e < 8; e++) acc = fmaf(s[e], Wb[e * 64 + t], acc);
    } else if (t < 128) {
        const int o = t - 64;
        acc = br[o];
        #pragma unroll 8
        for (int e = 0; e < 64; e++) acc = fmaf(s[8 + e], Wr[e * 64 + o], acc);
    } else {
        const int o = t - 128;
        acc = bt[o];
        #pragma unroll 8
        for (int e = 0; e < 64; e++) acc = fmaf(s[72 + e], Wt[e * 64 + o], acc);
    }
    d_E[n * 192 + t] = fmaxf(acc, 0.0f);
}

// ---------------- generic tiled fp32 GEMM ----------------
template <int ACT>
__global__ __launch_bounds__(256) void gemm_kernel(const float* __restrict__ A,
                                                   const float* __restrict__ W,
                                                   const float* __restrict__ bias,
                                                   float* __restrict__ C,
                                                   int Kd, int Nc)
{
    __shared__ float As[16][64];
    __shared__ float Ws[16][64];
    const int m0 = blockIdx.x * 64;
    const int n0 = blockIdx.y * 64;
    const int tid = threadIdx.x;
    const int tx = tid & 15;
    const int ty = tid >> 4;

    float acc[4][4];
    #pragma unroll
    for (int i = 0; i < 4; i++)
        #pragma unroll
        for (int j = 0; j < 4; j++) acc[i][j] = 0.0f;

    for (int k0 = 0; k0 < Kd; k0 += 16) {
        {
            const int m  = tid >> 2;
            const int kq = (tid & 3) * 4;
            float4 v = *reinterpret_cast<const float4*>(&A[(m0 + m) * Kd + k0 + kq]);
            As[kq + 0][m] = v.x; As[kq + 1][m] = v.y;
            As[kq + 2][m] = v.z; As[kq + 3][m] = v.w;
            const int kk = tid >> 4;
            const int nq = (tid & 15) * 4;
            float4 w = *reinterpret_cast<const float4*>(&W[(k0 + kk) * Nc + n0 + nq]);
            *reinterpret_cast<float4*>(&Ws[kk][nq]) = w;
        }
        __syncthreads();
        #pragma unroll
        for (int k = 0; k < 16; k++) {
            float4 a = *reinterpret_cast<const float4*>(&As[k][ty * 4]);
            float4 b = *reinterpret_cast<const float4*>(&Ws[k][tx * 4]);
            float av[4] = {a.x, a.y, a.z, a.w};
            float bv[4] = {b.x, b.y, b.z, b.w};
            #pragma unroll
            for (int i = 0; i < 4; i++)
                #pragma unroll
                for (int j = 0; j < 4; j++)
                    acc[i][j] = fmaf(av[i], bv[j], acc[i][j]);
        }
        __syncthreads();
    }

    #pragma unroll
    for (int i = 0; i < 4; i++) {
        const int m = m0 + ty * 4 + i;
        #pragma unroll
        for (int j = 0; j < 4; j++) {
            const int n = n0 + tx * 4 + j;
            float v = acc[i][j] + (bias ? bias[n] : 0.0f);
            if (ACT == 2) v = (v > 0.0f) ? v : 0.01f * v;
            C[m * Nc + n] = v;
        }
    }
}

// ---------------- fused: bf16 cast (to d_X2) + exact fp32 squared norms ----------
template <int D>
__global__ void splitsq_kernel(const float* __restrict__ X, float* __restrict__ sqn)
{
    constexpr int PL = D / 32;
    const int wid  = threadIdx.x >> 5;
    const int lane = threadIdx.x & 31;
    const int n    = blockIdx.x * 8 + wid;

    float v[PL];
    if constexpr (PL == 4) {
        float4 t = *reinterpret_cast<const float4*>(&X[n * D + lane * 4]);
        v[0] = t.x; v[1] = t.y; v[2] = t.z; v[3] = t.w;
    } else {
        float2 t = *reinterpret_cast<const float2*>(&X[n * D + lane * 2]);
        v[0] = t.x; v[1] = t.y;
    }

    float s = 0.0f;
    #pragma unroll
    for (int i = 0; i < PL; i++) s = fmaf(v[i], v[i], s);
    #pragma unroll
    for (int o = 16; o > 0; o >>= 1) s += __shfl_xor_sync(0xFFFFFFFFu, s, o);
    if (lane == 0) sqn[n] = s;

    if constexpr (PL == 4) {
        __nv_bfloat162 h0 = __floats2bfloat162_rn(v[0], v[1]);
        __nv_bfloat162 h1 = __floats2bfloat162_rn(v[2], v[3]);
        *reinterpret_cast<__nv_bfloat162*>(&d_X2[n * D + lane * 4])     = h0;
        *reinterpret_cast<__nv_bfloat162*>(&d_X2[n * D + lane * 4 + 2]) = h1;
    } else {
        __nv_bfloat162 h0 = __floats2bfloat162_rn(v[0], v[1]);
        *reinterpret_cast<__nv_bfloat162*>(&d_X2[n * D + lane * 2]) = h0;
    }
}

// ---------------- top-k insert (generic length) ----------------
template <int M>
__device__ __forceinline__ void topk_insert(float (&topd)[M], int (&topi)[M],
                                            float dd, int ci)
{
    topd[M - 1] = dd; topi[M - 1] = ci;
    #pragma unroll
    for (int z = M - 2; z >= 0; z--) {
        if (topd[z] > topd[z + 1]) {
            float td = topd[z]; topd[z] = topd[z + 1]; topd[z + 1] = td;
            int   ti = topi[z]; topi[z] = topi[z + 1]; topi[z + 1] = ti;
        }
    }
}

// ---------------- approx KNN via mma.sync (single-term bf16 Gram), 512 threads ----
// 128 queries/block, 128-candidate tiles, 16 warps; warp = 32q x 32c patch.
// fp32 dist, SINGLE buffer, 2 barriers/tile; scan of tile t-1 overlaps MMA(t).
template <int D>
__global__ __launch_bounds__(512, 1) void knn_mma_kernel(const float* __restrict__ sqn,
                                                         int* __restrict__ outCand)
{
    constexpr int PAD   = 8;
    constexpr int PB    = (D + PAD) * 2;        // tile smem row pitch in bytes
    constexpr int TILEB = 128 * PB;
    constexpr int CH    = D / 8;                // 16B chunks per row

    extern __shared__ char smch[];
    char* qt  = smch;
    char* ct0 = smch + TILEB;
    char* ct1 = smch + 2 * TILEB;
    float* dist = reinterpret_cast<float*>(smch + 3 * TILEB);  // 128*132 floats

    __shared__ float s_sqc[2][128];
    __shared__ float s_mg [128 * CAND];
    __shared__ int   s_mgi[128 * CAND];

    const int tid  = threadIdx.x;
    const int wid  = tid >> 5;
    const int lane = tid & 31;
    const int q0   = blockIdx.x * 128;

    const int mrow = (wid & 3) * 32;            // warp's query-row base
    const int ncol = (wid >> 2) * 32;           // warp's candidate-col base
    const int lrow = lane & 15;
    const int lkof = (lane >> 4) * 16;

    const uint32_t qtu  = smem_u32(qt);
    const uint32_t ctu0 = smem_u32(ct0);
    const uint32_t ctu1 = smem_u32(ct1);
    const uint32_t aBase = qtu + (mrow + lrow) * PB + lkof;
    const uint32_t bOff  = (ncol + lrow) * PB + lkof;

    {
        #pragma unroll
        for (int i = tid; i < 128 * CH; i += 512) {
            const int r  = i / CH;
            const int ch = i - r * CH;
            CP_ASYNC16(qtu + r * PB + ch * 16,
                       d_X2 + (size_t)(q0 + r) * D + ch * 8);
        }
        #pragma unroll
        for (int i = tid; i < 128 * CH; i += 512) {
            const int r  = i / CH;
            const int ch = i - r * CH;
            CP_ASYNC16(ctu0 + r * PB + ch * 16,
                       d_X2 + (size_t)r * D + ch * 8);
        }
        CP_COMMIT();
        if (tid < 128) s_sqc[0][tid] = sqn[tid];
    }

    float topd[CAND]; int topi[CAND];
    #pragma unroll
    for (int i = 0; i < CAND; i++) { topd[i] = 1e30f; topi[i] = 0; }

    const int qmine = tid & 127;     // query owned for scanning
    const int grp   = tid >> 7;      // 0..3: quarter of the candidate tile
    const int cbase = grp * 32;

    // scan 32 fp32 distances of one query row from dist (tile base cp0)
    auto scan_row = [&](int cp0) {
        const float* row = &dist[qmine * 132 + cbase];
        #pragma unroll
        for (int cc = 0; cc < 8; cc++) {
            float4 v = *reinterpret_cast<const float4*>(&row[cc * 4]);
            const int ci = cp0 + cbase + cc * 4;
            if (v.x < topd[CAND - 1]) topk_insert(topd, topi, v.x, ci + 0);
            if (v.y < topd[CAND - 1]) topk_insert(topd, topi, v.y, ci + 1);
            if (v.z < topd[CAND - 1]) topk_insert(topd, topi, v.z, ci + 2);
            if (v.w < topd[CAND - 1]) topk_insert(topd, topi, v.w, ci + 3);
        }
    };

    const int T = N_NODES / 128;
    for (int t = 0; t < T; t++) {
        CP_WAIT0();
        __syncthreads();   // ct(t) resident; dist(t-1) writes visible

        const uint32_t ctu = (t & 1) ? ctu1 : ctu0;
        if (t + 1 < T) {
            const uint32_t ctn = ((t + 1) & 1) ? ctu1 : ctu0;
            const int r0n = (t + 1) * 128;
            #pragma unroll
            for (int i = tid; i < 128 * CH; i += 512) {
                const int r  = i / CH;
                const int ch = i - r * CH;
                CP_ASYNC16(ctn + r * PB + ch * 16,
                           d_X2 + (size_t)(r0n + r) * D + ch * 8);
            }
            CP_COMMIT();
            if (tid < 128) s_sqc[(t + 1) & 1][tid] = sqn[r0n + tid];
        }

        // ---- Gram: warp 32q x 32c, m16n8k16 atoms ----
        float acc[2][4][4];
        #pragma unroll
        for (int mt = 0; mt < 2; mt++)
            #pragma unroll
            for (int nt = 0; nt < 4; nt++)
                #pragma unroll
                for (int r = 0; r < 4; r++) acc[mt][nt][r] = 0.0f;

        const uint32_t bBase = ctu + bOff;
        #pragma unroll
        for (int kc = 0; kc < D; kc += 16) {
            uint32_t a[2][4];
            #pragma unroll
            for (int mt = 0; mt < 2; mt++)
                LDSM4(a[mt][0], a[mt][1], a[mt][2], a[mt][3],
                      aBase + mt * 16 * PB + kc * 2);
            uint32_t b[4][2];
            #pragma unroll
            for (int nb = 0; nb < 2; nb++) {
                uint32_t r0, r1, r2, r3;
                LDSM4(r0, r1, r2, r3, bBase + nb * 16 * PB + kc * 2);
                b[nb * 2][0] = r0; b[nb * 2][1] = r2;
                b[nb * 2 + 1][0] = r1; b[nb * 2 + 1][1] = r3;
            }
            #pragma unroll
            for (int mt = 0; mt < 2; mt++)
                #pragma unroll
                for (int nt = 0; nt < 4; nt++)
                    MMA16816(acc[mt][nt], a[mt], b[nt]);
        }

        // ---- scan dist(t-1) — independent of MMA(t); fills its latency ----
        if (t > 0) scan_row((t - 1) * 128);
        __syncthreads();   // all scans done before dist rewrite

        // ---- write dist(t), fp32 ----
        const float* sq = s_sqc[t & 1];
        const int c0 = t * 128;

        #pragma unroll
        for (int mt = 0; mt < 2; mt++) {
            const int qA = mrow + mt * 16 + (lane >> 2);
            #pragma unroll
            for (int nt = 0; nt < 4; nt++) {
                const int c = ncol + nt * 8 + (lane & 3) * 2;
                const float s0 = sq[c], s1 = sq[c + 1];
                float2 v0, v1;
                v0.x = fmaf(-2.0f, acc[mt][nt][0], s0);
                v0.y = fmaf(-2.0f, acc[mt][nt][1], s1);
                v1.x = fmaf(-2.0f, acc[mt][nt][2], s0);
                v1.y = fmaf(-2.0f, acc[mt][nt][3], s1);
                const int dq = (q0 + qA) - (c0 + c);
                if (dq ==  0) v0.x = 1e30f;
                if (dq ==  1) v0.y = 1e30f;
                if (dq == -8) v1.x = 1e30f;
                if (dq == -7) v1.y = 1e30f;
                *reinterpret_cast<float2*>(&dist[qA * 132 + c])       = v0;
                *reinterpret_cast<float2*>(&dist[(qA + 8) * 132 + c]) = v1;
            }
        }
    }

    // final tile's scan
    __syncthreads();
    scan_row((T - 1) * 128);

    // ---- merge the four per-query quarters (3 rounds through one buffer) ----
    #pragma unroll 1
    for (int s = 1; s < 4; s++) {
        __syncthreads();
        if (grp == s) {
            #pragma unroll
            for (int i = 0; i < CAND; i++) {
                s_mg [qmine * CAND + i] = topd[i];
                s_mgi[qmine * CAND + i] = topi[i];
            }
        }
        __syncthreads();
        if (grp == 0) {
            #pragma unroll
            for (int i = 0; i < CAND; i++) {
                const float dd = s_mg[qmine * CAND + i];
                if (dd < topd[CAND - 1]) topk_insert(topd, topi, dd, s_mgi[qmine * CAND + i]);
            }
        }
    }
    if (grp == 0) {
        #pragma unroll
        for (int i = 0; i < CAND; i++) outCand[(q0 + qmine) * CAND + i] = topi[i];
    }
}

// ---------------- exact fp32 rescore: top-KNN of CAND candidates per query -------
template <int D>
__global__ void rescore_kernel(const float* __restrict__ X, const float* __restrict__ sqn,
                               const int* __restrict__ cand, int* __restrict__ outIdx)
{
    constexpr int PL = D / 32;
    const int wid  = threadIdx.x >> 5;
    const int lane = threadIdx.x & 31;
    const int q    = blockIdx.x * 8 + wid;

    float xq[PL];
    #pragma unroll
    for (int i = 0; i < PL; i++) xq[i] = X[q * D + i * 32 + lane];

    float topd[KNN]; int topi[KNN];
    #pragma unroll
    for (int i = 0; i < KNN; i++) { topd[i] = 1e30f; topi[i] = 0; }

    #pragma unroll
    for (int j = 0; j < CAND; j++) {
        const int c = cand[q * CAND + j];
        float dot = 0.0f;
        #pragma unroll
        for (int i = 0; i < PL; i++) dot = fmaf(xq[i], X[c * D + i * 32 + lane], dot);
        #pragma unroll
        for (int o = 16; o > 0; o >>= 1) dot += __shfl_xor_sync(0xFFFFFFFFu, dot, o);
        const float dd = fmaf(-2.0f, dot, sqn[c]);
        if (dd < topd[KNN - 1]) topk_insert(topd, topi, dd, c);
    }
    if (lane == 0) {
        #pragma unroll
        for (int i = 0; i < KNN; i++) outIdx[q * KNN + i] = topi[i];
    }
}

// ---------------- EdgeConv weight split: WP = Wa - Wb, WQ = Wb ----------------
__global__ void prepw_kernel(const float* __restrict__ We, int D)
{
    const int i = blockIdx.x * 256 + threadIdx.x;
    if (i < D * 64) {
        const float b = We[D * 64 + i];
        d_WQ[i] = b;
        d_WP[i] = We[i] - b;
    }
}

// ---------------- EdgeConv aggregation ----------------
__global__ void maxagg_kernel(const float* __restrict__ P, const float* __restrict__ Q,
                              const int* __restrict__ idx, float* __restrict__ g)
{
    const int tid = threadIdx.x;
    const int n = blockIdx.x * 4 + (tid >> 6);
    const int o = tid & 63;
    const float p = P[n * 64 + o];
    float m = -1e30f;
    #pragma unroll
    for (int kk = 0; kk < KNN; kk++) {
        const int j = idx[n * KNN + kk];
        float v = p + Q[j * 64 + o];
        v = (v > 0.0f) ? v : 0.01f * v;
        m = fmaxf(m, v);
    }
    g[n * 64 + o] = m;
}

// ---------------- classifier ----------------
__global__ void classifier_kernel(const float* __restrict__ Wc, const float* __restrict__ bc,
                                  float* __restrict__ out)
{
    const int tid = threadIdx.x;
    const int n = blockIdx.x * 16 + (tid >> 4);
    const int c = tid & 15;
    float acc = bc[c];
    const float* g1r = d_g1 + n * 64;
    const float* g2r = d_g2 + n * 64;
    #pragma unroll 8
    for (int o = 0; o < 64; o++) {
        acc = fmaf(g1r[o], Wc[o * 16 + c], acc);
        acc = fmaf(g2r[o], Wc[(64 + o) * 16 + c], acc);
    }
    out[n * 16 + c] = acc;
}

// ---------------- launch ----------------
extern "C" void kernel_launch(void* const* d_in, const int* in_sizes, int n_in,
                              void* d_out, int out_size)
{
    const float* node_feat = (const float*)d_in[0];
    const float* rf_feat   = (const float*)d_in[1];
    const float* txp_feat  = (const float*)d_in[2];
    const float* Wb  = (const float*)d_in[3];
    const float* bb  = (const float*)d_in[4];
    const float* Wr  = (const float*)d_in[5];
    const float* br  = (const float*)d_in[6];
    const float* Wt  = (const float*)d_in[7];
    const float* bt  = (const float*)d_in[8];
    const float* Wf  = (const float*)d_in[9];
    const float* bf  = (const float*)d_in[10];
    const float* We1 = (const float*)d_in[11];
    const float* be1 = (const float*)d_in[12];
    const float* We2 = (const float*)d_in[13];
    const float* be2 = (const float*)d_in[14];
    const float* Wc  = (const float*)d_in[15];
    const float* bc  = (const float*)d_in[16];
    float* out = (float*)d_out;

    void *pE, *pH, *pg1, *pg2, *pP, *pQ, *psqn, *pidx, *pcand, *pWP, *pWQ;
    cudaGetSymbolAddress(&pE,    d_E);
    cudaGetSymbolAddress(&pH,    d_H);
    cudaGetSymbolAddress(&pg1,   d_g1);
    cudaGetSymbolAddress(&pg2,   d_g2);
    cudaGetSymbolAddress(&pP,    d_P);
    cudaGetSymbolAddress(&pQ,    d_Qm);
    cudaGetSymbolAddress(&psqn,  d_sqn);
    cudaGetSymbolAddress(&pidx,  d_idx);
    cudaGetSymbolAddress(&pcand, d_cand);
    cudaGetSymbolAddress(&pWP,   d_WP);
    cudaGetSymbolAddress(&pWQ,   d_WQ);

    // D=128: 3 tiles x 34816B + fp32 dist 67584B = 172032B dynamic
    // D=64 : 3 tiles x 18432B + fp32 dist 67584B = 122880B dynamic
    const int smem1 = 3 * 128 * 272 + 128 * 132 * 4;
    const int smem2 = 3 * 128 * 144 + 128 * 132 * 4;
    cudaFuncSetAttribute(knn_mma_kernel<128>, cudaFuncAttributeMaxDynamicSharedMemorySize, smem1);
    cudaFuncSetAttribute(knn_mma_kernel<64>,  cudaFuncAttributeMaxDynamicSharedMemorySize, smem2);

    // stage 1: embeds + fusion   (launch order keeps knn<128> at profiled slot #4)
    embed_kernel<<<N_NODES, 192>>>(node_feat, rf_feat, txp_feat, Wb, bb, Wr, br, Wt, bt);
    gemm_kernel<2><<<dim3(N_NODES / 64, 2), 256>>>((const float*)pE, Wf, bf, (float*)pH, 192, 128);

    // EdgeConv 1
    splitsq_kernel<128><<<N_NODES / 8, 256>>>((const float*)pH, (float*)psqn);
    knn_mma_kernel<128><<<128, 512, smem1>>>((const float*)psqn, (int*)pcand);
    rescore_kernel<128><<<N_NODES / 8, 256>>>((const float*)pH, (const float*)psqn,
                                              (const int*)pcand, (int*)pidx);
    prepw_kernel<<<(128 * 64 + 255) / 256, 256>>>(We1, 128);
    gemm_kernel<0><<<dim3(N_NODES / 64, 1), 256>>>((const float*)pH, (const float*)pWP, be1,
                                                   (float*)pP, 128, 64);
    gemm_kernel<0><<<dim3(N_NODES / 64, 1), 256>>>((const float*)pH, (const float*)pWQ, nullptr,
                                                   (float*)pQ, 128, 64);
    maxagg_kernel<<<N_NODES / 4, 256>>>((const float*)pP, (const float*)pQ,
                                        (const int*)pidx, (float*)pg1);

    // EdgeConv 2
    splitsq_kernel<64><<<N_NODES / 8, 256>>>((const float*)pg1, (float*)psqn);
    knn_mma_kernel<64><<<128, 512, smem2>>>((const float*)psqn, (int*)pcand);
    rescore_kernel<64><<<N_NODES / 8, 256>>>((const float*)pg1, (const float*)psqn,
                                             (const int*)pcand, (int*)pidx);
    prepw_kernel<<<(64 * 64 + 255) / 256, 256>>>(We2, 64);
    gemm_kernel<0><<<dim3(N_NODES / 64, 1), 256>>>((const float*)pg1, (const float*)pWP, be2,
                                                   (float*)pP, 64, 64);
    gemm_kernel<0><<<dim3(N_NODES / 64, 1), 256>>>((const float*)pg1, (const float*)pWQ, nullptr,
                                                   (float*)pQ, 64, 64);
    maxagg_kernel<<<N_NODES / 4, 256>>>((const float*)pP, (const float*)pQ,
                                        (const int*)pidx, (float*)pg2);

    // classifier
    classifier_kernel<<<N_NODES / 16, 256>>>(Wc, bc, out);
}

// round 10
// speedup vs baseline: 4.0975x; 1.8268x over previous
#include <cuda_runtime.h>
#include <cuda_bf16.h>
#include <cstdint>

#define N_NODES 16384
#define KNN 10
#define CAND 16   // approx candidates kept per query for exact rescoring

// ---------------- scratch (static device allocations; no runtime alloc) ----------------
__device__ float d_E [N_NODES * 192];
__device__ float d_H [N_NODES * 128];
__device__ float d_g1[N_NODES * 64];
__device__ float d_g2[N_NODES * 64];
__device__ float d_P [N_NODES * 64];
__device__ float d_Qm[N_NODES * 64];
__device__ float d_sqn[N_NODES];
__device__ int   d_idx[N_NODES * KNN];
__device__ int   d_cand[N_NODES * CAND];
__device__ float d_WP[128 * 64];
__device__ float d_WQ[128 * 64];
__device__ __nv_bfloat16 d_X2[N_NODES * 128];   // bf16(x), up to 128 cols

// ---------------- PTX helpers (generic sm_80+ features only) ----------------
__device__ __forceinline__ uint32_t smem_u32(const void* p) {
    uint32_t a;
    asm("{ .reg .u64 t; cvta.to.shared.u64 t, %1; cvt.u32.u64 %0, t; }" : "=r"(a) : "l"(p));
    return a;
}
#define CP_ASYNC16(dst, src) \
    asm volatile("cp.async.cg.shared.global [%0], [%1], 16;" :: "r"(dst), "l"(src))
#define CP_COMMIT() asm volatile("cp.async.commit_group;" ::: "memory")
#define CP_WAIT0()  asm volatile("cp.async.wait_group 0;" ::: "memory")

#define LDSM4(r0, r1, r2, r3, addr) \
    asm volatile("ldmatrix.sync.aligned.m8n8.x4.shared.b16 {%0,%1,%2,%3}, [%4];" \
                 : "=r"(r0), "=r"(r1), "=r"(r2), "=r"(r3) : "r"(addr))

#define MMA16816(d, a, b) \
    asm volatile("mma.sync.aligned.m16n8k16.row.col.f32.bf16.bf16.f32 " \
                 "{%0,%1,%2,%3}, {%4,%5,%6,%7}, {%8,%9}, {%0,%1,%2,%3};" \
                 : "+f"((d)[0]), "+f"((d)[1]), "+f"((d)[2]), "+f"((d)[3]) \
                 : "r"((a)[0]), "r"((a)[1]), "r"((a)[2]), "r"((a)[3]), \
                   "r"((b)[0]), "r"((b)[1]))

// ---------------- stage 1: per-modality embeds (relu) -> E[N,192] ----------------
__global__ void embed_kernel(const float* __restrict__ nf, const float* __restrict__ rf,
                             const float* __restrict__ tf,
                             const float* __restrict__ Wb, const float* __restrict__ bb,
                             const float* __restrict__ Wr, const float* __restrict__ br,
                             const float* __restrict__ Wt, const float* __restrict__ bt)
{
    __shared__ float s[136];
    const int n = blockIdx.x;
    const int t = threadIdx.x;
    if (t < 8)                 s[t]            = nf[n * 8 + t];
    if (t >= 64 && t < 128)    s[8 + (t - 64)] = rf[n * 64 + (t - 64)];
    if (t >= 128)              s[72 + (t-128)] = tf[n * 64 + (t - 128)];
    __syncthreads();

    float acc;
    if (t < 64) {
        acc = bb[t];
        #pragma unroll
        for (int e = 0; e < 8; e++) acc = fmaf(s[e], Wb[e * 64 + t], acc);
    } else if (t < 128) {
        const int o = t - 64;
        acc = br[o];
        #pragma unroll 8
        for (int e = 0; e < 64; e++) acc = fmaf(s[8 + e], Wr[e * 64 + o], acc);
    } else {
        const int o = t - 128;
        acc = bt[o];
        #pragma unroll 8
        for (int e = 0; e < 64; e++) acc = fmaf(s[72 + e], Wt[e * 64 + o], acc);
    }
    d_E[n * 192 + t] = fmaxf(acc, 0.0f);
}

// ---------------- generic tiled fp32 GEMM ----------------
template <int ACT>
__global__ __launch_bounds__(256) void gemm_kernel(const float* __restrict__ A,
                                                   const float* __restrict__ W,
                                                   const float* __restrict__ bias,
                                                   float* __restrict__ C,
                                                   int Kd, int Nc)
{
    __shared__ float As[16][64];
    __shared__ float Ws[16][64];
    const int m0 = blockIdx.x * 64;
    const int n0 = blockIdx.y * 64;
    const int tid = threadIdx.x;
    const int tx = tid & 15;
    const int ty = tid >> 4;

    float acc[4][4];
    #pragma unroll
    for (int i = 0; i < 4; i++)
        #pragma unroll
        for (int j = 0; j < 4; j++) acc[i][j] = 0.0f;

    for (int k0 = 0; k0 < Kd; k0 += 16) {
        {
            const int m  = tid >> 2;
            const int kq = (tid & 3) * 4;
            float4 v = *reinterpret_cast<const float4*>(&A[(m0 + m) * Kd + k0 + kq]);
            As[kq + 0][m] = v.x; As[kq + 1][m] = v.y;
            As[kq + 2][m] = v.z; As[kq + 3][m] = v.w;
            const int kk = tid >> 4;
            const int nq = (tid & 15) * 4;
            float4 w = *reinterpret_cast<const float4*>(&W[(k0 + kk) * Nc + n0 + nq]);
            *reinterpret_cast<float4*>(&Ws[kk][nq]) = w;
        }
        __syncthreads();
        #pragma unroll
        for (int k = 0; k < 16; k++) {
            float4 a = *reinterpret_cast<const float4*>(&As[k][ty * 4]);
            float4 b = *reinterpret_cast<const float4*>(&Ws[k][tx * 4]);
            float av[4] = {a.x, a.y, a.z, a.w};
            float bv[4] = {b.x, b.y, b.z, b.w};
            #pragma unroll
            for (int i = 0; i < 4; i++)
                #pragma unroll
                for (int j = 0; j < 4; j++)
                    acc[i][j] = fmaf(av[i], bv[j], acc[i][j]);
        }
        __syncthreads();
    }

    #pragma unroll
    for (int i = 0; i < 4; i++) {
        const int m = m0 + ty * 4 + i;
        #pragma unroll
        for (int j = 0; j < 4; j++) {
            const int n = n0 + tx * 4 + j;
            float v = acc[i][j] + (bias ? bias[n] : 0.0f);
            if (ACT == 2) v = (v > 0.0f) ? v : 0.01f * v;
            C[m * Nc + n] = v;
        }
    }
}

// ---------------- fused: bf16 cast (to d_X2) + exact fp32 squared norms ----------
template <int D>
__global__ void splitsq_kernel(const float* __restrict__ X, float* __restrict__ sqn)
{
    constexpr int PL = D / 32;
    const int wid  = threadIdx.x >> 5;
    const int lane = threadIdx.x & 31;
    const int n    = blockIdx.x * 8 + wid;

    float v[PL];
    if constexpr (PL == 4) {
        float4 t = *reinterpret_cast<const float4*>(&X[n * D + lane * 4]);
        v[0] = t.x; v[1] = t.y; v[2] = t.z; v[3] = t.w;
    } else {
        float2 t = *reinterpret_cast<const float2*>(&X[n * D + lane * 2]);
        v[0] = t.x; v[1] = t.y;
    }

    float s = 0.0f;
    #pragma unroll
    for (int i = 0; i < PL; i++) s = fmaf(v[i], v[i], s);
    #pragma unroll
    for (int o = 16; o > 0; o >>= 1) s += __shfl_xor_sync(0xFFFFFFFFu, s, o);
    if (lane == 0) sqn[n] = s;

    if constexpr (PL == 4) {
        __nv_bfloat162 h0 = __floats2bfloat162_rn(v[0], v[1]);
        __nv_bfloat162 h1 = __floats2bfloat162_rn(v[2], v[3]);
        *reinterpret_cast<__nv_bfloat162*>(&d_X2[n * D + lane * 4])     = h0;
        *reinterpret_cast<__nv_bfloat162*>(&d_X2[n * D + lane * 4 + 2]) = h1;
    } else {
        __nv_bfloat162 h0 = __floats2bfloat162_rn(v[0], v[1]);
        *reinterpret_cast<__nv_bfloat162*>(&d_X2[n * D + lane * 2]) = h0;
    }
}

// ---------------- top-k insert (generic length) ----------------
template <int M>
__device__ __forceinline__ void topk_insert(float (&topd)[M], int (&topi)[M],
                                            float dd, int ci)
{
    topd[M - 1] = dd; topi[M - 1] = ci;
    #pragma unroll
    for (int z = M - 2; z >= 0; z--) {
        if (topd[z] > topd[z + 1]) {
            float td = topd[z]; topd[z] = topd[z + 1]; topd[z + 1] = td;
            int   ti = topi[z]; topi[z] = topi[z + 1]; topi[z + 1] = ti;
        }
    }
}

// ---------------- approx KNN via mma.sync (single-term bf16 Gram), 512 threads ----
// 128 queries/block, 128-candidate tiles, 16 warps; warp = 32q x 32c patch.
// fp32 dist, single buffer; scan via argmin-loop: branchless (min,argmin) pass,
// ONE insert site per round (all lanes' inserts SIMD), poison slot, repeat.
template <int D>
__global__ __launch_bounds__(512, 1) void knn_mma_kernel(const float* __restrict__ sqn,
                                                         int* __restrict__ outCand)
{
    constexpr int PAD   = 8;
    constexpr int PB    = (D + PAD) * 2;        // tile smem row pitch in bytes
    constexpr int TILEB = 128 * PB;
    constexpr int CH    = D / 8;                // 16B chunks per row

    extern __shared__ char smch[];
    char* qt  = smch;
    char* ct0 = smch + TILEB;
    char* ct1 = smch + 2 * TILEB;
    float* dist = reinterpret_cast<float*>(smch + 3 * TILEB);  // 128*132 floats

    __shared__ float s_sqc[2][128];
    __shared__ float s_mg [128 * CAND];
    __shared__ int   s_mgi[128 * CAND];

    const int tid  = threadIdx.x;
    const int wid  = tid >> 5;
    const int lane = tid & 31;
    const int q0   = blockIdx.x * 128;

    const int mrow = (wid & 3) * 32;            // warp's query-row base
    const int ncol = (wid >> 2) * 32;           // warp's candidate-col base
    const int lrow = lane & 15;
    const int lkof = (lane >> 4) * 16;

    const uint32_t qtu  = smem_u32(qt);
    const uint32_t ctu0 = smem_u32(ct0);
    const uint32_t ctu1 = smem_u32(ct1);
    const uint32_t aBase = qtu + (mrow + lrow) * PB + lkof;
    const uint32_t bOff  = (ncol + lrow) * PB + lkof;

    {
        #pragma unroll
        for (int i = tid; i < 128 * CH; i += 512) {
            const int r  = i / CH;
            const int ch = i - r * CH;
            CP_ASYNC16(qtu + r * PB + ch * 16,
                       d_X2 + (size_t)(q0 + r) * D + ch * 8);
        }
        #pragma unroll
        for (int i = tid; i < 128 * CH; i += 512) {
            const int r  = i / CH;
            const int ch = i - r * CH;
            CP_ASYNC16(ctu0 + r * PB + ch * 16,
                       d_X2 + (size_t)r * D + ch * 8);
        }
        CP_COMMIT();
        if (tid < 128) s_sqc[0][tid] = sqn[tid];
    }

    float topd[CAND]; int topi[CAND];
    #pragma unroll
    for (int i = 0; i < CAND; i++) { topd[i] = 1e30f; topi[i] = 0; }

    const int qmine = tid & 127;     // query owned for scanning
    const int grp   = tid >> 7;      // 0..3: quarter of the candidate tile
    const int cbase = grp * 32;

    // argmin-loop scan of this thread's 32-candidate segment (tile base cp0).
    // Branchless (min,argmin) pass; single insert site; poison slot; repeat.
    float* const myrow = &dist[(tid & 127) * 132 + cbase];
    auto scan_row = [&](int cp0) {
        while (true) {
            float bm = 1e30f; int ba = 0;
            #pragma unroll
            for (int cc = 0; cc < 8; cc++) {
                float4 v = *reinterpret_cast<const float4*>(&myrow[cc * 4]);
                if (v.x < bm) { bm = v.x; ba = cc * 4 + 0; }
                if (v.y < bm) { bm = v.y; ba = cc * 4 + 1; }
                if (v.z < bm) { bm = v.z; ba = cc * 4 + 2; }
                if (v.w < bm) { bm = v.w; ba = cc * 4 + 3; }
            }
            if (bm >= topd[CAND - 1]) break;
            topk_insert(topd, topi, bm, cp0 + cbase + ba);
            myrow[ba] = 1e30f;   // remove from pool (thread-exclusive segment)
        }
    };

    const int T = N_NODES / 128;
    for (int t = 0; t < T; t++) {
        CP_WAIT0();
        __syncthreads();   // ct(t) resident; dist(t-1) writes visible

        const uint32_t ctu = (t & 1) ? ctu1 : ctu0;
        if (t + 1 < T) {
            const uint32_t ctn = ((t + 1) & 1) ? ctu1 : ctu0;
            const int r0n = (t + 1) * 128;
            #pragma unroll
            for (int i = tid; i < 128 * CH; i += 512) {
                const int r  = i / CH;
                const int ch = i - r * CH;
                CP_ASYNC16(ctn + r * PB + ch * 16,
                           d_X2 + (size_t)(r0n + r) * D + ch * 8);
            }
            CP_COMMIT();
            if (tid < 128) s_sqc[(t + 1) & 1][tid] = sqn[r0n + tid];
        }

        // ---- Gram: warp 32q x 32c, m16n8k16 atoms ----
        float acc[2][4][4];
        #pragma unroll
        for (int mt = 0; mt < 2; mt++)
            #pragma unroll
            for (int nt = 0; nt < 4; nt++)
                #pragma unroll
                for (int r = 0; r < 4; r++) acc[mt][nt][r] = 0.0f;

        const uint32_t bBase = ctu + bOff;
        #pragma unroll
        for (int kc = 0; kc < D; kc += 16) {
            uint32_t a[2][4];
            #pragma unroll
            for (int mt = 0; mt < 2; mt++)
                LDSM4(a[mt][0], a[mt][1], a[mt][2], a[mt][3],
                      aBase + mt * 16 * PB + kc * 2);
            uint32_t b[4][2];
            #pragma unroll
            for (int nb = 0; nb < 2; nb++) {
                uint32_t r0, r1, r2, r3;
                LDSM4(r0, r1, r2, r3, bBase + nb * 16 * PB + kc * 2);
                b[nb * 2][0] = r0; b[nb * 2][1] = r2;
                b[nb * 2 + 1][0] = r1; b[nb * 2 + 1][1] = r3;
            }
            #pragma unroll
            for (int mt = 0; mt < 2; mt++)
                #pragma unroll
                for (int nt = 0; nt < 4; nt++)
                    MMA16816(acc[mt][nt], a[mt], b[nt]);
        }

        // ---- scan dist(t-1) — independent of MMA(t); fills its latency ----
        if (t > 0) scan_row((t - 1) * 128);
        __syncthreads();   // all scans done before dist rewrite

        // ---- write dist(t), fp32 ----
        const float* sq = s_sqc[t & 1];
        const int c0 = t * 128;

        #pragma unroll
        for (int mt = 0; mt < 2; mt++) {
            const int qA = mrow + mt * 16 + (lane >> 2);
            #pragma unroll
            for (int nt = 0; nt < 4; nt++) {
                const int c = ncol + nt * 8 + (lane & 3) * 2;
                const float s0 = sq[c], s1 = sq[c + 1];
                float2 v0, v1;
                v0.x = fmaf(-2.0f, acc[mt][nt][0], s0);
                v0.y = fmaf(-2.0f, acc[mt][nt][1], s1);
                v1.x = fmaf(-2.0f, acc[mt][nt][2], s0);
                v1.y = fmaf(-2.0f, acc[mt][nt][3], s1);
                const int dq = (q0 + qA) - (c0 + c);
                if (dq ==  0) v0.x = 1e30f;
                if (dq ==  1) v0.y = 1e30f;
                if (dq == -8) v1.x = 1e30f;
                if (dq == -7) v1.y = 1e30f;
                *reinterpret_cast<float2*>(&dist[qA * 132 + c])       = v0;
                *reinterpret_cast<float2*>(&dist[(qA + 8) * 132 + c]) = v1;
            }
        }
    }

    // final tile's scan
    __syncthreads();
    scan_row((T - 1) * 128);

    // ---- merge the four per-query quarters (3 rounds through one buffer) ----
    #pragma unroll 1
    for (int s = 1; s < 4; s++) {
        __syncthreads();
        if (grp == s) {
            #pragma unroll
            for (int i = 0; i < CAND; i++) {
                s_mg [qmine * CAND + i] = topd[i];
                s_mgi[qmine * CAND + i] = topi[i];
            }
        }
        __syncthreads();
        if (grp == 0) {
            #pragma unroll
            for (int i = 0; i < CAND; i++) {
                const float dd = s_mg[qmine * CAND + i];
                if (dd < topd[CAND - 1]) topk_insert(topd, topi, dd, s_mgi[qmine * CAND + i]);
            }
        }
    }
    if (grp == 0) {
        #pragma unroll
        for (int i = 0; i < CAND; i++) outCand[(q0 + qmine) * CAND + i] = topi[i];
    }
}

// ---------------- exact fp32 rescore: top-KNN of CAND candidates per query -------
template <int D>
__global__ void rescore_kernel(const float* __restrict__ X, const float* __restrict__ sqn,
                               const int* __restrict__ cand, int* __restrict__ outIdx)
{
    constexpr int PL = D / 32;
    const int wid  = threadIdx.x >> 5;
    const int lane = threadIdx.x & 31;
    const int q    = blockIdx.x * 8 + wid;

    float xq[PL];
    #pragma unroll
    for (int i = 0; i < PL; i++) xq[i] = X[q * D + i * 32 + lane];

    float topd[KNN]; int topi[KNN];
    #pragma unroll
    for (int i = 0; i < KNN; i++) { topd[i] = 1e30f; topi[i] = 0; }

    #pragma unroll
    for (int j = 0; j < CAND; j++) {
        const int c = cand[q * CAND + j];
        float dot = 0.0f;
        #pragma unroll
        for (int i = 0; i < PL; i++) dot = fmaf(xq[i], X[c * D + i * 32 + lane], dot);
        #pragma unroll
        for (int o = 16; o > 0; o >>= 1) dot += __shfl_xor_sync(0xFFFFFFFFu, dot, o);
        const float dd = fmaf(-2.0f, dot, sqn[c]);
        if (dd < topd[KNN - 1]) topk_insert(topd, topi, dd, c);
    }
    if (lane == 0) {
        #pragma unroll
        for (int i = 0; i < KNN; i++) outIdx[q * KNN + i] = topi[i];
    }
}

// ---------------- EdgeConv weight split: WP = Wa - Wb, WQ = Wb ----------------
__global__ void prepw_kernel(const float* __restrict__ We, int D)
{
    const int i = blockIdx.x * 256 + threadIdx.x;
    if (i < D * 64) {
        const float b = We[D * 64 + i];
        d_WQ[i] = b;
        d_WP[i] = We[i] - b;
    }
}

// ---------------- EdgeConv aggregation ----------------
__global__ void maxagg_kernel(const float* __restrict__ P, const float* __restrict__ Q,
                              const int* __restrict__ idx, float* __restrict__ g)
{
    const int tid = threadIdx.x;
    const int n = blockIdx.x * 4 + (tid >> 6);
    const int o = tid & 63;
    const float p = P[n * 64 + o];
    float m = -1e30f;
    #pragma unroll
    for (int kk = 0; kk < KNN; kk++) {
        const int j = idx[n * KNN + kk];
        float v = p + Q[j * 64 + o];
        v = (v > 0.0f) ? v : 0.01f * v;
        m = fmaxf(m, v);
    }
    g[n * 64 + o] = m;
}

// ---------------- classifier ----------------
__global__ void classifier_kernel(const float* __restrict__ Wc, const float* __restrict__ bc,
                                  float* __restrict__ out)
{
    const int tid = threadIdx.x;
    const int n = blockIdx.x * 16 + (tid >> 4);
    const int c = tid & 15;
    float acc = bc[c];
    const float* g1r = d_g1 + n * 64;
    const float* g2r = d_g2 + n * 64;
    #pragma unroll 8
    for (int o = 0; o < 64; o++) {
        acc = fmaf(g1r[o], Wc[o * 16 + c], acc);
        acc = fmaf(g2r[o], Wc[(64 + o) * 16 + c], acc);
    }
    out[n * 16 + c] = acc;
}

// ---------------- launch ----------------
extern "C" void kernel_launch(void* const* d_in, const int* in_sizes, int n_in,
                              void* d_out, int out_size)
{
    const float* node_feat = (const float*)d_in[0];
    const float* rf_feat   = (const float*)d_in[1];
    const float* txp_feat  = (const float*)d_in[2];
    const float* Wb  = (const float*)d_in[3];
    const float* bb  = (const float*)d_in[4];
    const float* Wr  = (const float*)d_in[5];
    const float* br  = (const float*)d_in[6];
    const float* Wt  = (const float*)d_in[7];
    const float* bt  = (const float*)d_in[8];
    const float* Wf  = (const float*)d_in[9];
    const float* bf  = (const float*)d_in[10];
    const float* We1 = (const float*)d_in[11];
    const float* be1 = (const float*)d_in[12];
    const float* We2 = (const float*)d_in[13];
    const float* be2 = (const float*)d_in[14];
    const float* Wc  = (const float*)d_in[15];
    const float* bc  = (const float*)d_in[16];
    float* out = (float*)d_out;

    void *pE, *pH, *pg1, *pg2, *pP, *pQ, *psqn, *pidx, *pcand, *pWP, *pWQ;
    cudaGetSymbolAddress(&pE,    d_E);
    cudaGetSymbolAddress(&pH,    d_H);
    cudaGetSymbolAddress(&pg1,   d_g1);
    cudaGetSymbolAddress(&pg2,   d_g2);
    cudaGetSymbolAddress(&pP,    d_P);
    cudaGetSymbolAddress(&pQ,    d_Qm);
    cudaGetSymbolAddress(&psqn,  d_sqn);
    cudaGetSymbolAddress(&pidx,  d_idx);
    cudaGetSymbolAddress(&pcand, d_cand);
    cudaGetSymbolAddress(&pWP,   d_WP);
    cudaGetSymbolAddress(&pWQ,   d_WQ);

    // D=128: 3 tiles x 34816B + fp32 dist 67584B = 172032B dynamic
    // D=64 : 3 tiles x 18432B + fp32 dist 67584B = 122880B dynamic
    const int smem1 = 3 * 128 * 272 + 128 * 132 * 4;
    const int smem2 = 3 * 128 * 144 + 128 * 132 * 4;
    cudaFuncSetAttribute(knn_mma_kernel<128>, cudaFuncAttributeMaxDynamicSharedMemorySize, smem1);
    cudaFuncSetAttribute(knn_mma_kernel<64>,  cudaFuncAttributeMaxDynamicSharedMemorySize, smem2);

    // stage 1: embeds + fusion   (launch order keeps knn<128> at profiled slot #4)
    embed_kernel<<<N_NODES, 192>>>(node_feat, rf_feat, txp_feat, Wb, bb, Wr, br, Wt, bt);
    gemm_kernel<2><<<dim3(N_NODES / 64, 2), 256>>>((const float*)pE, Wf, bf, (float*)pH, 192, 128);

    // EdgeConv 1
    splitsq_kernel<128><<<N_NODES / 8, 256>>>((const float*)pH, (float*)psqn);
    knn_mma_kernel<128><<<128, 512, smem1>>>((const float*)psqn, (int*)pcand);
    rescore_kernel<128><<<N_NODES / 8, 256>>>((const float*)pH, (const float*)psqn,
                                              (const int*)pcand, (int*)pidx);
    prepw_kernel<<<(128 * 64 + 255) / 256, 256>>>(We1, 128);
    gemm_kernel<0><<<dim3(N_NODES / 64, 1), 256>>>((const float*)pH, (const float*)pWP, be1,
                                                   (float*)pP, 128, 64);
    gemm_kernel<0><<<dim3(N_NODES / 64, 1), 256>>>((const float*)pH, (const float*)pWQ, nullptr,
                                                   (float*)pQ, 128, 64);
    maxagg_kernel<<<N_NODES / 4, 256>>>((const float*)pP, (const float*)pQ,
                                        (const int*)pidx, (float*)pg1);

    // EdgeConv 2
    splitsq_kernel<64><<<N_NODES / 8, 256>>>((const float*)pg1, (float*)psqn);
    knn_mma_kernel<64><<<128, 512, smem2>>>((const float*)psqn, (int*)pcand);
    rescore_kernel<64><<<N_NODES / 8, 256>>>((const float*)pg1, (const float*)psqn,
                                             (const int*)pcand, (int*)pidx);
    prepw_kernel<<<(64 * 64 + 255) / 256, 256>>>(We2, 64);
    gemm_kernel<0><<<dim3(N_NODES / 64, 1), 256>>>((const float*)pg1, (const float*)pWP, be2,
                                                   (float*)pP, 64, 64);
    gemm_kernel<0><<<dim3(N_NODES / 64, 1), 256>>>((const float*)pg1, (const float*)pWQ, nullptr,
                                                   (float*)pQ, 64, 64);
    maxagg_kernel<<<N_NODES / 4, 256>>>((const float*)pP, (const float*)pQ,
                                        (const int*)pidx, (float*)pg2);

    // classifier
    classifier_kernel<<<N_NODES / 16, 256>>>(Wc, bc, out);
}